// round 4
// baseline (speedup 1.0000x reference)
#include <cuda_runtime.h>
#include <cstdint>
#include <cstddef>

#define NN 20000
#define NE 320000
#define ALPHA 0.2f

// ---------------- scratch (device globals; no allocation allowed) ------------
__device__ __align__(16) float g_B[1024 * 1024];          // repacked weight matrix
__device__ __align__(16) float g_Wh[(size_t)NN * 1024];   // per-layer Wh (N x H*F)
__device__ __align__(16) float g_x1[(size_t)NN * 1024];
__device__ __align__(16) float g_x2[(size_t)NN * 1024];
__device__ __align__(16) float g_h[(size_t)NN * 1024];    // aggregation target
__device__ __align__(16) float g_ssrc[6 * NN];
__device__ __align__(16) float g_sdst[6 * NN];
__device__ __align__(16) unsigned g_emax[6 * NN];         // ordered-encoded float max
__device__ __align__(16) float g_esum[6 * NN];
__device__ __align__(16) float g_att[(size_t)6 * NE];
__device__ __align__(16) int g_srcI[NE];
__device__ __align__(16) int g_dstI[NE];
__device__ int g_is64;

// ---------------- helpers ----------------------------------------------------
__device__ __forceinline__ unsigned encOrd(float f) {
    unsigned u = __float_as_uint(f);
    return (u & 0x80000000u) ? ~u : (u | 0x80000000u);
}
__device__ __forceinline__ float decOrd(unsigned u) {
    return (u & 0x80000000u) ? __uint_as_float(u ^ 0x80000000u) : __uint_as_float(~u);
}
__device__ __forceinline__ float eluf(float z) {
    return z > 0.f ? z : expm1f(z);
}

// ---------------- edge index dtype probe + conversion -------------------------
// If the buffer is真 int64, every 8-byte word holds a value in [0, N).
// If it is int32, an 8-byte read packs two indices; whenever the high word is
// nonzero (prob 1 - 1/20000 per element) the value is >= 2^32 >= N.
__global__ void detect_k(const void* __restrict__ ei, int N) {
    const long long* p = (const long long*)ei;
    int ok64 = 1;
    for (int i = 0; i < 1024; i++) {
        long long v = p[i];
        if (v < 0 || v >= N) { ok64 = 0; break; }
    }
    g_is64 = ok64;
}

__global__ void conv_edges(const void* __restrict__ ei, int* __restrict__ s,
                           int* __restrict__ d, int E) {
    int i = blockIdx.x * blockDim.x + threadIdx.x;
    if (i >= E) return;
    if (g_is64) {
        const long long* p = (const long long*)ei;
        s[i] = (int)p[i];
        d[i] = (int)p[E + i];
    } else {
        const int* p = (const int*)ei;
        s[i] = p[i];
        d[i] = p[E + i];
    }
}

// ---------------- small utility kernels --------------------------------------
__global__ void zero_f4(float4* p, size_t n4) {
    size_t i = (size_t)blockIdx.x * blockDim.x + threadIdx.x;
    if (i < n4) p[i] = make_float4(0.f, 0.f, 0.f, 0.f);
}

// W (H,K,F) -> B (K, H*FP) with zero padding f in [F, FP)
__global__ void repack_w(const float* __restrict__ W, float* __restrict__ B,
                         int K, int H, int F, int FP) {
    int total = K * H * FP;
    int idx = blockIdx.x * blockDim.x + threadIdx.x;
    if (idx >= total) return;
    int hf = H * FP;
    int k = idx / hf;
    int rem = idx - k * hf;
    int h = rem / FP;
    int f = rem - h * FP;
    B[idx] = (f < F) ? W[((size_t)h * K + k) * F + f] : 0.f;
}

// ---------------- SGEMM: C[M,N] = A[M,K] * B[K,N] ----------------------------
#define BM 128
#define BN 128
#define BKK 8
#define TM 8
#define TN 8
__global__ __launch_bounds__(256) void sgemm_k(int M, int N, int K,
                                               const float* __restrict__ A,
                                               const float* __restrict__ B,
                                               float* __restrict__ C) {
    __shared__ float As[BKK][BM];
    __shared__ float Bs[BKK][BN];
    const int tid = threadIdx.x;
    const int bm = blockIdx.y * BM, bn = blockIdx.x * BN;
    const int arow = tid >> 1;          // 0..127
    const int acol = (tid & 1) * 4;     // 0 or 4
    const int brow = tid >> 5;          // 0..7
    const int bcol = (tid & 31) * 4;    // 0..124
    const int trow = (tid >> 4) * TM;
    const int tcol = (tid & 15) * TN;

    float acc[TM][TN];
#pragma unroll
    for (int i = 0; i < TM; i++)
#pragma unroll
        for (int j = 0; j < TN; j++) acc[i][j] = 0.f;

    for (int k0 = 0; k0 < K; k0 += BKK) {
        int gar = bm + arow;
#pragma unroll
        for (int j = 0; j < 4; j++) {
            int gk = k0 + acol + j;
            As[acol + j][arow] = (gar < M && gk < K) ? A[(size_t)gar * K + gk] : 0.f;
        }
        int gbr = k0 + brow;
        if (gbr < K) {
            float4 v = *(const float4*)(B + (size_t)gbr * N + bn + bcol);
            Bs[brow][bcol + 0] = v.x;
            Bs[brow][bcol + 1] = v.y;
            Bs[brow][bcol + 2] = v.z;
            Bs[brow][bcol + 3] = v.w;
        } else {
            Bs[brow][bcol + 0] = 0.f;
            Bs[brow][bcol + 1] = 0.f;
            Bs[brow][bcol + 2] = 0.f;
            Bs[brow][bcol + 3] = 0.f;
        }
        __syncthreads();

#pragma unroll
        for (int kk = 0; kk < BKK; kk++) {
            float ra[TM], rb[TN];
#pragma unroll
            for (int i = 0; i < TM; i++) ra[i] = As[kk][trow + i];
#pragma unroll
            for (int j = 0; j < TN; j++) rb[j] = Bs[kk][tcol + j];
#pragma unroll
            for (int i = 0; i < TM; i++)
#pragma unroll
                for (int j = 0; j < TN; j++) acc[i][j] += ra[i] * rb[j];
        }
        __syncthreads();
    }

#pragma unroll
    for (int i = 0; i < TM; i++) {
        int gr = bm + trow + i;
        if (gr < M) {
            float4 v0 = make_float4(acc[i][0], acc[i][1], acc[i][2], acc[i][3]);
            float4 v1 = make_float4(acc[i][4], acc[i][5], acc[i][6], acc[i][7]);
            *(float4*)(C + (size_t)gr * N + bn + tcol) = v0;
            *(float4*)(C + (size_t)gr * N + bn + tcol + 4) = v1;
        }
    }
}

// ---------------- attention scores per node ----------------------------------
__global__ void score_k(int N, int H, int F, int ld, int hs, int astride,
                        const float* __restrict__ Wh, const float* __restrict__ a,
                        float* __restrict__ ssrc, float* __restrict__ sdst) {
    int gw = (blockIdx.x * blockDim.x + threadIdx.x) >> 5;
    int lane = threadIdx.x & 31;
    if (gw >= N * H) return;
    int n = gw / H, h = gw - n * H;
    const float* row = Wh + (size_t)n * ld + h * hs;
    const float* av = a + (size_t)h * astride;
    float s1 = 0.f, s2 = 0.f;
    for (int f = lane; f < F; f += 32) {
        float v = row[f];
        s1 += v * av[f];
        s2 += v * av[F + f];
    }
#pragma unroll
    for (int o = 16; o; o >>= 1) {
        s1 += __shfl_xor_sync(0xffffffffu, s1, o);
        s2 += __shfl_xor_sync(0xffffffffu, s2, o);
    }
    if (lane == 0) {
        ssrc[h * N + n] = s1;
        sdst[h * N + n] = s2;
    }
}

// ---------------- edge passes -------------------------------------------------
__global__ void edgeA_k(int E, int N, int H,
                        const int* __restrict__ src, const int* __restrict__ dst,
                        const float* __restrict__ ssrc, const float* __restrict__ sdst,
                        float* __restrict__ att, unsigned* __restrict__ emax) {
    int i = blockIdx.x * blockDim.x + threadIdx.x;
    if (i >= E * H) return;
    int e = i % E, h = i / E;
    int s = src[e], d = dst[e];
    float v = ssrc[h * N + s] + sdst[h * N + d];
    v = v > 0.f ? v : ALPHA * v;
    att[i] = v;
    atomicMax(&emax[h * N + d], encOrd(v));
}

__global__ void edgeB_k(int E, int N, int H, const int* __restrict__ dst,
                        float* __restrict__ att, const unsigned* __restrict__ emax,
                        float* __restrict__ esum) {
    int i = blockIdx.x * blockDim.x + threadIdx.x;
    if (i >= E * H) return;
    int e = i % E, h = i / E;
    int d = dst[e];
    float m = decOrd(emax[h * N + d]);
    float w = __expf(att[i] - m);
    att[i] = w;
    atomicAdd(&esum[h * N + d], w);
}

// one warp per (edge, head): out[dst] += att * Wh[src]
__global__ void scatter_k(int E, int N, int H, int nf4, int ld, int hs,
                          int outld, int ouths,
                          const int* __restrict__ src, const int* __restrict__ dst,
                          const float* __restrict__ att, const float* __restrict__ esum,
                          const float* __restrict__ Wh, float* __restrict__ out) {
    int gw = (blockIdx.x * blockDim.x + threadIdx.x) >> 5;
    if (gw >= E * H) return;
    int lane = threadIdx.x & 31;
    int e = gw % E, h = gw / E;
    int s = src[e], d = dst[e];
    float w = att[(size_t)h * E + e];
    float at = w / (esum[h * N + d] + 1e-16f);
    const float4* rp = (const float4*)(Wh + (size_t)s * ld + h * hs);
    float* op = out + (size_t)d * outld + h * ouths;
    for (int j = lane; j < nf4; j += 32) {
        float4 v = rp[j];
        atomicAdd(op + j * 4 + 0, v.x * at);
        atomicAdd(op + j * 4 + 1, v.y * at);
        atomicAdd(op + j * 4 + 2, v.z * at);
        atomicAdd(op + j * 4 + 3, v.w * at);
    }
}

// ---------------- epilogues ---------------------------------------------------
__global__ void epi1_k(const float* __restrict__ h, float* __restrict__ x1, size_t cnt) {
    size_t i = (size_t)blockIdx.x * blockDim.x + threadIdx.x;
    if (i < cnt) x1[i] = eluf(eluf(h[i]));
}
__global__ void epi2_k(const float* __restrict__ h, const float* __restrict__ x1,
                       float* __restrict__ x2, size_t cnt) {
    size_t i = (size_t)blockIdx.x * blockDim.x + threadIdx.x;
    if (i < cnt) x2[i] = eluf(eluf(h[i]) + x1[i]);
}
__global__ void final_k(const float* __restrict__ h3, float* __restrict__ out, int N) {
    int i = blockIdx.x * blockDim.x + threadIdx.x;
    if (i >= N * 121) return;
    int n = i / 121, f = i - n * 121;
    float v = h3[(size_t)n * 128 + f] * (1.f / 6.f);
    out[i] = 1.f / (1.f + __expf(-v));
}

// ---------------- driver ------------------------------------------------------
extern "C" void kernel_launch(void* const* d_in, const int* in_sizes, int n_in,
                              void* d_out, int out_size) {
    const float* x = (const float*)d_in[0];
    const void* ei = d_in[1];
    const float* W1 = (const float*)d_in[2];
    const float* a1 = (const float*)d_in[3];
    const float* W2 = (const float*)d_in[4];
    const float* a2 = (const float*)d_in[5];
    const float* W3 = (const float*)d_in[6];
    const float* a3 = (const float*)d_in[7];
    float* out = (float*)d_out;

    float *B, *Wh, *x1, *x2, *hb, *ssrc, *sdst, *esum, *att;
    unsigned* emax;
    int *srcI, *dstI;
    cudaGetSymbolAddress((void**)&B, g_B);
    cudaGetSymbolAddress((void**)&Wh, g_Wh);
    cudaGetSymbolAddress((void**)&x1, g_x1);
    cudaGetSymbolAddress((void**)&x2, g_x2);
    cudaGetSymbolAddress((void**)&hb, g_h);
    cudaGetSymbolAddress((void**)&ssrc, g_ssrc);
    cudaGetSymbolAddress((void**)&sdst, g_sdst);
    cudaGetSymbolAddress((void**)&emax, g_emax);
    cudaGetSymbolAddress((void**)&esum, g_esum);
    cudaGetSymbolAddress((void**)&att, g_att);
    cudaGetSymbolAddress((void**)&srcI, g_srcI);
    cudaGetSymbolAddress((void**)&dstI, g_dstI);

    const int N = NN, E = NE;
    const int TB = 256;

    detect_k<<<1, 1>>>(ei, N);
    conv_edges<<<(E + TB - 1) / TB, TB>>>(ei, srcI, dstI, E);

    // ============ Layer 1: K=50, H=4, F=256, Ntot=1024 ============
    {
        int K = 50, H = 4, F = 256, FP = 256, Ntot = 1024;
        repack_w<<<(K * H * FP + TB - 1) / TB, TB>>>(W1, B, K, H, F, FP);
        dim3 g(Ntot / BN, (N + BM - 1) / BM);
        sgemm_k<<<g, 256>>>(N, Ntot, K, x, B, Wh);
        score_k<<<(N * H * 32 + TB - 1) / TB, TB>>>(N, H, F, Ntot, F, 2 * F, Wh, a1, ssrc, sdst);
        zero_f4<<<((size_t)N * Ntot / 4 + TB - 1) / TB, TB>>>((float4*)hb, (size_t)N * Ntot / 4);
        zero_f4<<<(H * N / 4 + TB - 1) / TB, TB>>>((float4*)emax, H * N / 4);
        zero_f4<<<(H * N / 4 + TB - 1) / TB, TB>>>((float4*)esum, H * N / 4);
        edgeA_k<<<(E * H + TB - 1) / TB, TB>>>(E, N, H, srcI, dstI, ssrc, sdst, att, emax);
        edgeB_k<<<(E * H + TB - 1) / TB, TB>>>(E, N, H, dstI, att, emax, esum);
        scatter_k<<<((size_t)E * H * 32 + TB - 1) / TB, TB>>>(E, N, H, F / 4, Ntot, F, Ntot, F,
                                                             srcI, dstI, att, esum, Wh, hb);
        epi1_k<<<((size_t)N * Ntot + TB - 1) / TB, TB>>>(hb, x1, (size_t)N * Ntot);
    }

    // ============ Layer 2: K=1024, H=4, F=256, Ntot=1024, skip ============
    {
        int K = 1024, H = 4, F = 256, FP = 256, Ntot = 1024;
        repack_w<<<(K * H * FP + TB - 1) / TB, TB>>>(W2, B, K, H, F, FP);
        dim3 g(Ntot / BN, (N + BM - 1) / BM);
        sgemm_k<<<g, 256>>>(N, Ntot, K, x1, B, Wh);
        score_k<<<(N * H * 32 + TB - 1) / TB, TB>>>(N, H, F, Ntot, F, 2 * F, Wh, a2, ssrc, sdst);
        zero_f4<<<((size_t)N * Ntot / 4 + TB - 1) / TB, TB>>>((float4*)hb, (size_t)N * Ntot / 4);
        zero_f4<<<(H * N / 4 + TB - 1) / TB, TB>>>((float4*)emax, H * N / 4);
        zero_f4<<<(H * N / 4 + TB - 1) / TB, TB>>>((float4*)esum, H * N / 4);
        edgeA_k<<<(E * H + TB - 1) / TB, TB>>>(E, N, H, srcI, dstI, ssrc, sdst, att, emax);
        edgeB_k<<<(E * H + TB - 1) / TB, TB>>>(E, N, H, dstI, att, emax, esum);
        scatter_k<<<((size_t)E * H * 32 + TB - 1) / TB, TB>>>(E, N, H, F / 4, Ntot, F, Ntot, F,
                                                             srcI, dstI, att, esum, Wh, hb);
        epi2_k<<<((size_t)N * Ntot + TB - 1) / TB, TB>>>(hb, x1, x2, (size_t)N * Ntot);
    }

    // ============ Layer 3: K=1024, H=6, F=121 (pad 128), mean heads ============
    {
        int K = 1024, H = 6, F = 121, FP = 128, Ntot = 768;
        repack_w<<<(K * H * FP + TB - 1) / TB, TB>>>(W3, B, K, H, F, FP);
        dim3 g(Ntot / BN, (N + BM - 1) / BM);
        sgemm_k<<<g, 256>>>(N, Ntot, K, x2, B, Wh);
        score_k<<<(N * H * 32 + TB - 1) / TB, TB>>>(N, H, F, Ntot, FP, 2 * F, Wh, a3, ssrc, sdst);
        zero_f4<<<((size_t)N * FP / 4 + TB - 1) / TB, TB>>>((float4*)hb, (size_t)N * FP / 4);
        zero_f4<<<(H * N / 4 + TB - 1) / TB, TB>>>((float4*)emax, H * N / 4);
        zero_f4<<<(H * N / 4 + TB - 1) / TB, TB>>>((float4*)esum, H * N / 4);
        edgeA_k<<<(E * H + TB - 1) / TB, TB>>>(E, N, H, srcI, dstI, ssrc, sdst, att, emax);
        edgeB_k<<<(E * H + TB - 1) / TB, TB>>>(E, N, H, dstI, att, emax, esum);
        // all heads accumulate into the SAME (N,128) buffer (mean later);
        // padded cols 121..127 of Wh are zero so full-width adds are harmless.
        scatter_k<<<((size_t)E * H * 32 + TB - 1) / TB, TB>>>(E, N, H, FP / 4, Ntot, FP, FP, 0,
                                                             srcI, dstI, att, esum, Wh, hb);
        final_k<<<(N * 121 + TB - 1) / TB, TB>>>(hb, out, N);
    }
}

// round 5
// speedup vs baseline: 1.2706x; 1.2706x over previous
#include <cuda_runtime.h>
#include <cstdint>
#include <cstddef>

#define NN 20000
#define NE 320000
#define ALPHA 0.2f

// ---------------- scratch (device globals; no allocation allowed) ------------
__device__ __align__(16) float g_B[1024 * 1024];          // repacked weight matrix
__device__ __align__(16) float g_Wh[(size_t)NN * 1024];   // per-layer Wh (N x H*F)
__device__ __align__(16) float g_x1[(size_t)NN * 1024];
__device__ __align__(16) float g_x2[(size_t)NN * 1024];
__device__ __align__(16) float g_h[(size_t)NN * 1024];    // aggregation target
__device__ __align__(16) float g_ssrc[6 * NN];
__device__ __align__(16) float g_sdst[6 * NN];
__device__ __align__(16) unsigned g_emax[6 * NN];         // ordered-encoded float max
__device__ __align__(16) float g_esum[6 * NN];
__device__ __align__(16) float g_att[(size_t)6 * NE];
__device__ __align__(16) int g_srcI[NE];
__device__ __align__(16) int g_dstI[NE];
__device__ int g_is64;

// ---------------- helpers ----------------------------------------------------
__device__ __forceinline__ unsigned encOrd(float f) {
    unsigned u = __float_as_uint(f);
    return (u & 0x80000000u) ? ~u : (u | 0x80000000u);
}
__device__ __forceinline__ float decOrd(unsigned u) {
    return (u & 0x80000000u) ? __uint_as_float(u ^ 0x80000000u) : __uint_as_float(~u);
}
__device__ __forceinline__ float eluf(float z) {
    return z > 0.f ? z : expm1f(z);
}
__device__ __forceinline__ unsigned f2tf(float x) {
    unsigned r;
    asm("cvt.rna.tf32.f32 %0, %1;" : "=r"(r) : "f"(x));
    return r;
}

// ---------------- edge index dtype probe + conversion -------------------------
__global__ void detect_k(const void* __restrict__ ei, int N) {
    const long long* p = (const long long*)ei;
    int ok64 = 1;
    for (int i = 0; i < 1024; i++) {
        long long v = p[i];
        if (v < 0 || v >= N) { ok64 = 0; break; }
    }
    g_is64 = ok64;
}

__global__ void conv_edges(const void* __restrict__ ei, int* __restrict__ s,
                           int* __restrict__ d, int E) {
    int i = blockIdx.x * blockDim.x + threadIdx.x;
    if (i >= E) return;
    if (g_is64) {
        const long long* p = (const long long*)ei;
        s[i] = (int)p[i];
        d[i] = (int)p[E + i];
    } else {
        const int* p = (const int*)ei;
        s[i] = p[i];
        d[i] = p[E + i];
    }
}

// ---------------- small utility kernels --------------------------------------
__global__ void zero_f4(float4* p, size_t n4) {
    size_t i = (size_t)blockIdx.x * blockDim.x + threadIdx.x;
    if (i < n4) p[i] = make_float4(0.f, 0.f, 0.f, 0.f);
}

// W (H,K,F) -> B (K, H*FP) with zero padding f in [F, FP)
__global__ void repack_w(const float* __restrict__ W, float* __restrict__ B,
                         int K, int H, int F, int FP) {
    int total = K * H * FP;
    int idx = blockIdx.x * blockDim.x + threadIdx.x;
    if (idx >= total) return;
    int hf = H * FP;
    int k = idx / hf;
    int rem = idx - k * hf;
    int h = rem / FP;
    int f = rem - h * FP;
    B[idx] = (f < F) ? W[((size_t)h * K + k) * F + f] : 0.f;
}

// ---------------- TF32 tensor-core GEMM: C[M,N] = A[M,K] * B[K,N] -------------
// CTA tile 128x128x16, 8 warps (2m x 4n), warp tile 64x32, mma m16n8k8 tf32.
#define GBM 128
#define GBN 128
#define GBK 16
#define SAP 20   // padded stride (words) for As rows / Bs rows

__global__ __launch_bounds__(256) void gemm_tf32(int M, int N, int K,
                                                 const float* __restrict__ A,
                                                 const float* __restrict__ B,
                                                 float* __restrict__ C) {
    __shared__ unsigned As[2][GBM][SAP];   // [row][k] tf32 patterns
    __shared__ unsigned Bs[2][GBN][SAP];   // [n][k]  (transposed)

    const int tid = threadIdx.x;
    const int warp = tid >> 5;
    const int lane = tid & 31;
    const int g = lane >> 2;        // group id 0..7
    const int tig = lane & 3;       // thread-in-group 0..3
    const int wm = warp & 1;        // warp m index (0..1)
    const int wn = warp >> 1;       // warp n index (0..3)
    const int bm = blockIdx.y * GBM;
    const int bn = blockIdx.x * GBN;

    float acc[4][4][4];
#pragma unroll
    for (int mf = 0; mf < 4; mf++)
#pragma unroll
        for (int nf = 0; nf < 4; nf++)
#pragma unroll
            for (int r = 0; r < 4; r++) acc[mf][nf][r] = 0.f;

    const int KT = (K + GBK - 1) / GBK;
    unsigned pa[8], pb[8];

    // prologue: tile 0 -> regs
#pragma unroll
    for (int i = 0; i < 8; i++) {
        int idx = tid + i * 256;
        int ar = idx >> 4, ac = idx & 15;               // A: 128 rows x 16 k
        pa[i] = (bm + ar < M && ac < K) ? f2tf(A[(size_t)(bm + ar) * K + ac]) : 0u;
        int bk = idx >> 7, bnn = idx & 127;             // B: 16 k x 128 n
        pb[i] = (bk < K) ? f2tf(B[(size_t)bk * N + bn + bnn]) : 0u;
    }
#pragma unroll
    for (int i = 0; i < 8; i++) {
        int idx = tid + i * 256;
        As[0][idx >> 4][idx & 15] = pa[i];
        Bs[0][idx & 127][idx >> 7] = pb[i];
    }
    __syncthreads();

    for (int kt = 0; kt < KT; kt++) {
        const int buf = kt & 1;
        // prefetch next tile into regs (overlaps with compute)
        if (kt + 1 < KT) {
            const int gk = (kt + 1) * GBK;
#pragma unroll
            for (int i = 0; i < 8; i++) {
                int idx = tid + i * 256;
                int ar = idx >> 4, ac = idx & 15;
                pa[i] = (bm + ar < M && gk + ac < K)
                            ? f2tf(A[(size_t)(bm + ar) * K + gk + ac]) : 0u;
                int bk = idx >> 7, bnn = idx & 127;
                pb[i] = (gk + bk < K) ? f2tf(B[(size_t)(gk + bk) * N + bn + bnn]) : 0u;
            }
        }
        // compute on current buffer: 2 k8 steps
#pragma unroll
        for (int ks = 0; ks < 2; ks++) {
            const int kc = ks * 8;
            unsigned af[4][4], bf[4][2];
#pragma unroll
            for (int mf = 0; mf < 4; mf++) {
                int r = wm * 64 + mf * 16;
                af[mf][0] = As[buf][r + g][kc + tig];
                af[mf][1] = As[buf][r + g + 8][kc + tig];
                af[mf][2] = As[buf][r + g][kc + tig + 4];
                af[mf][3] = As[buf][r + g + 8][kc + tig + 4];
            }
#pragma unroll
            for (int nf = 0; nf < 4; nf++) {
                int c = wn * 32 + nf * 8 + g;
                bf[nf][0] = Bs[buf][c][kc + tig];
                bf[nf][1] = Bs[buf][c][kc + tig + 4];
            }
#pragma unroll
            for (int mf = 0; mf < 4; mf++)
#pragma unroll
                for (int nf = 0; nf < 4; nf++) {
                    asm volatile(
                        "mma.sync.aligned.m16n8k8.row.col.f32.tf32.tf32.f32 "
                        "{%0,%1,%2,%3}, {%4,%5,%6,%7}, {%8,%9}, {%0,%1,%2,%3};"
                        : "+f"(acc[mf][nf][0]), "+f"(acc[mf][nf][1]),
                          "+f"(acc[mf][nf][2]), "+f"(acc[mf][nf][3])
                        : "r"(af[mf][0]), "r"(af[mf][1]), "r"(af[mf][2]), "r"(af[mf][3]),
                          "r"(bf[nf][0]), "r"(bf[nf][1]));
                }
        }
        __syncthreads();   // all warps done reading buf^1 (from prev iter) & buf
        if (kt + 1 < KT) {
#pragma unroll
            for (int i = 0; i < 8; i++) {
                int idx = tid + i * 256;
                As[buf ^ 1][idx >> 4][idx & 15] = pa[i];
                Bs[buf ^ 1][idx & 127][idx >> 7] = pb[i];
            }
            __syncthreads();
        }
    }

    // epilogue
#pragma unroll
    for (int mf = 0; mf < 4; mf++) {
        int r0 = bm + wm * 64 + mf * 16 + g;
#pragma unroll
        for (int nf = 0; nf < 4; nf++) {
            int c0 = bn + wn * 32 + nf * 8 + tig * 2;
            if (r0 < M) {
                float2 v = make_float2(acc[mf][nf][0], acc[mf][nf][1]);
                *(float2*)(C + (size_t)r0 * N + c0) = v;
            }
            if (r0 + 8 < M) {
                float2 v = make_float2(acc[mf][nf][2], acc[mf][nf][3]);
                *(float2*)(C + (size_t)(r0 + 8) * N + c0) = v;
            }
        }
    }
}

// ---------------- attention scores per node ----------------------------------
__global__ void score_k(int N, int H, int F, int ld, int hs, int astride,
                        const float* __restrict__ Wh, const float* __restrict__ a,
                        float* __restrict__ ssrc, float* __restrict__ sdst) {
    int gw = (blockIdx.x * blockDim.x + threadIdx.x) >> 5;
    int lane = threadIdx.x & 31;
    if (gw >= N * H) return;
    int n = gw / H, h = gw - n * H;
    const float* row = Wh + (size_t)n * ld + h * hs;
    const float* av = a + (size_t)h * astride;
    float s1 = 0.f, s2 = 0.f;
    for (int f = lane; f < F; f += 32) {
        float v = row[f];
        s1 += v * av[f];
        s2 += v * av[F + f];
    }
#pragma unroll
    for (int o = 16; o; o >>= 1) {
        s1 += __shfl_xor_sync(0xffffffffu, s1, o);
        s2 += __shfl_xor_sync(0xffffffffu, s2, o);
    }
    if (lane == 0) {
        ssrc[h * N + n] = s1;
        sdst[h * N + n] = s2;
    }
}

// ---------------- edge passes -------------------------------------------------
__global__ void edgeA_k(int E, int N, int H,
                        const int* __restrict__ src, const int* __restrict__ dst,
                        const float* __restrict__ ssrc, const float* __restrict__ sdst,
                        float* __restrict__ att, unsigned* __restrict__ emax) {
    int i = blockIdx.x * blockDim.x + threadIdx.x;
    if (i >= E * H) return;
    int e = i % E, h = i / E;
    int s = src[e], d = dst[e];
    float v = ssrc[h * N + s] + sdst[h * N + d];
    v = v > 0.f ? v : ALPHA * v;
    att[i] = v;
    atomicMax(&emax[h * N + d], encOrd(v));
}

__global__ void edgeB_k(int E, int N, int H, const int* __restrict__ dst,
                        float* __restrict__ att, const unsigned* __restrict__ emax,
                        float* __restrict__ esum) {
    int i = blockIdx.x * blockDim.x + threadIdx.x;
    if (i >= E * H) return;
    int e = i % E, h = i / E;
    int d = dst[e];
    float m = decOrd(emax[h * N + d]);
    float w = __expf(att[i] - m);
    att[i] = w;
    atomicAdd(&esum[h * N + d], w);
}

// one warp per (edge, head): out[dst] += att * Wh[src]
__global__ void scatter_k(int E, int N, int H, int nf4, int ld, int hs,
                          int outld, int ouths,
                          const int* __restrict__ src, const int* __restrict__ dst,
                          const float* __restrict__ att, const float* __restrict__ esum,
                          const float* __restrict__ Wh, float* __restrict__ out) {
    int gw = (blockIdx.x * blockDim.x + threadIdx.x) >> 5;
    if (gw >= E * H) return;
    int lane = threadIdx.x & 31;
    int e = gw % E, h = gw / E;
    int s = src[e], d = dst[e];
    float w = att[(size_t)h * E + e];
    float at = w / (esum[h * N + d] + 1e-16f);
    const float4* rp = (const float4*)(Wh + (size_t)s * ld + h * hs);
    float* op = out + (size_t)d * outld + h * ouths;
    for (int j = lane; j < nf4; j += 32) {
        float4 v = rp[j];
        atomicAdd(op + j * 4 + 0, v.x * at);
        atomicAdd(op + j * 4 + 1, v.y * at);
        atomicAdd(op + j * 4 + 2, v.z * at);
        atomicAdd(op + j * 4 + 3, v.w * at);
    }
}

// ---------------- epilogues ---------------------------------------------------
__global__ void epi1_k(const float* __restrict__ h, float* __restrict__ x1, size_t cnt) {
    size_t i = (size_t)blockIdx.x * blockDim.x + threadIdx.x;
    if (i < cnt) x1[i] = eluf(eluf(h[i]));
}
__global__ void epi2_k(const float* __restrict__ h, const float* __restrict__ x1,
                       float* __restrict__ x2, size_t cnt) {
    size_t i = (size_t)blockIdx.x * blockDim.x + threadIdx.x;
    if (i < cnt) x2[i] = eluf(eluf(h[i]) + x1[i]);
}
__global__ void final_k(const float* __restrict__ h3, float* __restrict__ out, int N) {
    int i = blockIdx.x * blockDim.x + threadIdx.x;
    if (i >= N * 121) return;
    int n = i / 121, f = i - n * 121;
    float v = h3[(size_t)n * 128 + f] * (1.f / 6.f);
    out[i] = 1.f / (1.f + __expf(-v));
}

// ---------------- driver ------------------------------------------------------
extern "C" void kernel_launch(void* const* d_in, const int* in_sizes, int n_in,
                              void* d_out, int out_size) {
    const float* x = (const float*)d_in[0];
    const void* ei = d_in[1];
    const float* W1 = (const float*)d_in[2];
    const float* a1 = (const float*)d_in[3];
    const float* W2 = (const float*)d_in[4];
    const float* a2 = (const float*)d_in[5];
    const float* W3 = (const float*)d_in[6];
    const float* a3 = (const float*)d_in[7];
    float* out = (float*)d_out;

    float *B, *Wh, *x1, *x2, *hb, *ssrc, *sdst, *esum, *att;
    unsigned* emax;
    int *srcI, *dstI;
    cudaGetSymbolAddress((void**)&B, g_B);
    cudaGetSymbolAddress((void**)&Wh, g_Wh);
    cudaGetSymbolAddress((void**)&x1, g_x1);
    cudaGetSymbolAddress((void**)&x2, g_x2);
    cudaGetSymbolAddress((void**)&hb, g_h);
    cudaGetSymbolAddress((void**)&ssrc, g_ssrc);
    cudaGetSymbolAddress((void**)&sdst, g_sdst);
    cudaGetSymbolAddress((void**)&emax, g_emax);
    cudaGetSymbolAddress((void**)&esum, g_esum);
    cudaGetSymbolAddress((void**)&att, g_att);
    cudaGetSymbolAddress((void**)&srcI, g_srcI);
    cudaGetSymbolAddress((void**)&dstI, g_dstI);

    const int N = NN, E = NE;
    const int TB = 256;

    detect_k<<<1, 1>>>(ei, N);
    conv_edges<<<(E + TB - 1) / TB, TB>>>(ei, srcI, dstI, E);

    // ============ Layer 1: K=50, H=4, F=256, Ntot=1024 ============
    {
        int K = 50, H = 4, F = 256, FP = 256, Ntot = 1024;
        repack_w<<<(K * H * FP + TB - 1) / TB, TB>>>(W1, B, K, H, F, FP);
        dim3 g(Ntot / GBN, (N + GBM - 1) / GBM);
        gemm_tf32<<<g, 256>>>(N, Ntot, K, x, B, Wh);
        score_k<<<(N * H * 32 + TB - 1) / TB, TB>>>(N, H, F, Ntot, F, 2 * F, Wh, a1, ssrc, sdst);
        zero_f4<<<((size_t)N * Ntot / 4 + TB - 1) / TB, TB>>>((float4*)hb, (size_t)N * Ntot / 4);
        zero_f4<<<(H * N / 4 + TB - 1) / TB, TB>>>((float4*)emax, H * N / 4);
        zero_f4<<<(H * N / 4 + TB - 1) / TB, TB>>>((float4*)esum, H * N / 4);
        edgeA_k<<<(E * H + TB - 1) / TB, TB>>>(E, N, H, srcI, dstI, ssrc, sdst, att, emax);
        edgeB_k<<<(E * H + TB - 1) / TB, TB>>>(E, N, H, dstI, att, emax, esum);
        scatter_k<<<((size_t)E * H * 32 + TB - 1) / TB, TB>>>(E, N, H, F / 4, Ntot, F, Ntot, F,
                                                             srcI, dstI, att, esum, Wh, hb);
        epi1_k<<<((size_t)N * Ntot + TB - 1) / TB, TB>>>(hb, x1, (size_t)N * Ntot);
    }

    // ============ Layer 2: K=1024, H=4, F=256, Ntot=1024, skip ============
    {
        int K = 1024, H = 4, F = 256, FP = 256, Ntot = 1024;
        repack_w<<<(K * H * FP + TB - 1) / TB, TB>>>(W2, B, K, H, F, FP);
        dim3 g(Ntot / GBN, (N + GBM - 1) / GBM);
        gemm_tf32<<<g, 256>>>(N, Ntot, K, x1, B, Wh);
        score_k<<<(N * H * 32 + TB - 1) / TB, TB>>>(N, H, F, Ntot, F, 2 * F, Wh, a2, ssrc, sdst);
        zero_f4<<<((size_t)N * Ntot / 4 + TB - 1) / TB, TB>>>((float4*)hb, (size_t)N * Ntot / 4);
        zero_f4<<<(H * N / 4 + TB - 1) / TB, TB>>>((float4*)emax, H * N / 4);
        zero_f4<<<(H * N / 4 + TB - 1) / TB, TB>>>((float4*)esum, H * N / 4);
        edgeA_k<<<(E * H + TB - 1) / TB, TB>>>(E, N, H, srcI, dstI, ssrc, sdst, att, emax);
        edgeB_k<<<(E * H + TB - 1) / TB, TB>>>(E, N, H, dstI, att, emax, esum);
        scatter_k<<<((size_t)E * H * 32 + TB - 1) / TB, TB>>>(E, N, H, F / 4, Ntot, F, Ntot, F,
                                                             srcI, dstI, att, esum, Wh, hb);
        epi2_k<<<((size_t)N * Ntot + TB - 1) / TB, TB>>>(hb, x1, x2, (size_t)N * Ntot);
    }

    // ============ Layer 3: K=1024, H=6, F=121 (pad 128), mean heads ============
    {
        int K = 1024, H = 6, F = 121, FP = 128, Ntot = 768;
        repack_w<<<(K * H * FP + TB - 1) / TB, TB>>>(W3, B, K, H, F, FP);
        dim3 g(Ntot / GBN, (N + GBM - 1) / GBM);
        gemm_tf32<<<g, 256>>>(N, Ntot, K, x2, B, Wh);
        score_k<<<(N * H * 32 + TB - 1) / TB, TB>>>(N, H, F, Ntot, FP, 2 * F, Wh, a3, ssrc, sdst);
        zero_f4<<<((size_t)N * FP / 4 + TB - 1) / TB, TB>>>((float4*)hb, (size_t)N * FP / 4);
        zero_f4<<<(H * N / 4 + TB - 1) / TB, TB>>>((float4*)emax, H * N / 4);
        zero_f4<<<(H * N / 4 + TB - 1) / TB, TB>>>((float4*)esum, H * N / 4);
        edgeA_k<<<(E * H + TB - 1) / TB, TB>>>(E, N, H, srcI, dstI, ssrc, sdst, att, emax);
        edgeB_k<<<(E * H + TB - 1) / TB, TB>>>(E, N, H, dstI, att, emax, esum);
        // all heads accumulate into the SAME (N,128) buffer (mean later);
        // padded cols 121..127 of Wh are zero so full-width adds are harmless.
        scatter_k<<<((size_t)E * H * 32 + TB - 1) / TB, TB>>>(E, N, H, FP / 4, Ntot, FP, FP, 0,
                                                             srcI, dstI, att, esum, Wh, hb);
        final_k<<<(N * 121 + TB - 1) / TB, TB>>>(hb, out, N);
    }
}

// round 6
// speedup vs baseline: 2.2865x; 1.7996x over previous
#include <cuda_runtime.h>
#include <cstdint>
#include <cstddef>

#define NN 20000
#define NE 320000
#define ALPHA 0.2f

// ---------------- scratch (device globals; no allocation allowed) ------------
__device__ __align__(16) float g_B[1024 * 1024];          // repacked weight matrix
__device__ __align__(16) float g_Wh[(size_t)NN * 1024];   // per-layer Wh (N x H*F)
__device__ __align__(16) float g_x1[(size_t)NN * 1024];
__device__ __align__(16) float g_x2[(size_t)NN * 1024];
__device__ __align__(16) float g_h[(size_t)NN * 1024];    // aggregation target
__device__ __align__(16) float g_ssrc[6 * NN];
__device__ __align__(16) float g_sdst[6 * NN];
__device__ __align__(16) int g_srcI[NE];
__device__ __align__(16) int g_dstI[NE];
__device__ __align__(16) int g_cnt[NN];
__device__ __align__(16) int g_rowptr[NN + 4];
__device__ __align__(16) int g_cursor[NN];
__device__ __align__(16) int g_csrSrc[NE];
__device__ int g_is64;

// ---------------- helpers ----------------------------------------------------
__device__ __forceinline__ float eluf(float z) {
    return z > 0.f ? z : expm1f(z);
}
__device__ __forceinline__ unsigned f2tf(float x) {
    unsigned r;
    asm("cvt.rna.tf32.f32 %0, %1;" : "=r"(r) : "f"(x));
    return r;
}
__device__ __forceinline__ float lrelu(float v) {
    return v > 0.f ? v : ALPHA * v;
}

// ---------------- edge index dtype probe + conversion -------------------------
__global__ void detect_k(const void* __restrict__ ei, int N) {
    const long long* p = (const long long*)ei;
    int ok64 = 1;
    for (int i = 0; i < 1024; i++) {
        long long v = p[i];
        if (v < 0 || v >= N) { ok64 = 0; break; }
    }
    g_is64 = ok64;
}

__global__ void conv_edges(const void* __restrict__ ei, int* __restrict__ s,
                           int* __restrict__ d, int E) {
    int i = blockIdx.x * blockDim.x + threadIdx.x;
    if (i >= E) return;
    if (g_is64) {
        const long long* p = (const long long*)ei;
        s[i] = (int)p[i];
        d[i] = (int)p[E + i];
    } else {
        const int* p = (const int*)ei;
        s[i] = p[i];
        d[i] = p[E + i];
    }
}

// ---------------- CSR build ---------------------------------------------------
__global__ void zero_i(int* p, int n) {
    int i = blockIdx.x * blockDim.x + threadIdx.x;
    if (i < n) p[i] = 0;
}
__global__ void hist_k(const int* __restrict__ dst, int* __restrict__ cnt, int E) {
    int i = blockIdx.x * blockDim.x + threadIdx.x;
    if (i < E) atomicAdd(&cnt[dst[i]], 1);
}
// single-block inclusive scan -> exclusive rowptr
__global__ void scan_k(const int* __restrict__ cnt, int* __restrict__ rowptr, int n) {
    __shared__ int sh[1024];
    __shared__ int carry;
    int t = threadIdx.x;
    if (t == 0) { carry = 0; rowptr[0] = 0; }
    __syncthreads();
    for (int base = 0; base < n; base += 1024) {
        int v = (base + t < n) ? cnt[base + t] : 0;
        sh[t] = v;
        __syncthreads();
        for (int o = 1; o < 1024; o <<= 1) {
            int x = (t >= o) ? sh[t - o] : 0;
            __syncthreads();
            sh[t] += x;
            __syncthreads();
        }
        if (base + t < n) rowptr[base + t + 1] = sh[t] + carry;
        __syncthreads();
        if (t == 0) carry += sh[1023];
        __syncthreads();
    }
}
__global__ void copy_i(const int* __restrict__ a, int* __restrict__ b, int n) {
    int i = blockIdx.x * blockDim.x + threadIdx.x;
    if (i < n) b[i] = a[i];
}
__global__ void fill_k(const int* __restrict__ src, const int* __restrict__ dst,
                       int* __restrict__ cursor, int* __restrict__ csrSrc, int E) {
    int i = blockIdx.x * blockDim.x + threadIdx.x;
    if (i >= E) return;
    int pos = atomicAdd(&cursor[dst[i]], 1);
    csrSrc[pos] = src[i];
}

// ---------------- repack: W (H,K,F) -> B (K, H*FP), zero pad ------------------
__global__ void repack_w(const float* __restrict__ W, float* __restrict__ B,
                         int K, int H, int F, int FP) {
    int total = K * H * FP;
    int idx = blockIdx.x * blockDim.x + threadIdx.x;
    if (idx >= total) return;
    int hf = H * FP;
    int k = idx / hf;
    int rem = idx - k * hf;
    int h = rem / FP;
    int f = rem - h * FP;
    B[idx] = (f < F) ? W[((size_t)h * K + k) * F + f] : 0.f;
}

// ---------------- TF32 tensor-core GEMM: C[M,N] = A[M,K] * B[K,N] -------------
#define GBM 128
#define GBN 128
#define GBK 16
#define SAP 20

__global__ __launch_bounds__(256) void gemm_tf32(int M, int N, int K,
                                                 const float* __restrict__ A,
                                                 const float* __restrict__ B,
                                                 float* __restrict__ C) {
    __shared__ unsigned As[2][GBM][SAP];
    __shared__ unsigned Bs[2][GBN][SAP];

    const int tid = threadIdx.x;
    const int warp = tid >> 5;
    const int lane = tid & 31;
    const int g = lane >> 2;
    const int tig = lane & 3;
    const int wm = warp & 1;
    const int wn = warp >> 1;
    const int bm = blockIdx.y * GBM;
    const int bn = blockIdx.x * GBN;

    float acc[4][4][4];
#pragma unroll
    for (int mf = 0; mf < 4; mf++)
#pragma unroll
        for (int nf = 0; nf < 4; nf++)
#pragma unroll
            for (int r = 0; r < 4; r++) acc[mf][nf][r] = 0.f;

    const int KT = (K + GBK - 1) / GBK;
    unsigned pa[8], pb[8];

#pragma unroll
    for (int i = 0; i < 8; i++) {
        int idx = tid + i * 256;
        int ar = idx >> 4, ac = idx & 15;
        pa[i] = (bm + ar < M && ac < K) ? f2tf(A[(size_t)(bm + ar) * K + ac]) : 0u;
        int bk = idx >> 7, bnn = idx & 127;
        pb[i] = (bk < K) ? f2tf(B[(size_t)bk * N + bn + bnn]) : 0u;
    }
#pragma unroll
    for (int i = 0; i < 8; i++) {
        int idx = tid + i * 256;
        As[0][idx >> 4][idx & 15] = pa[i];
        Bs[0][idx & 127][idx >> 7] = pb[i];
    }
    __syncthreads();

    for (int kt = 0; kt < KT; kt++) {
        const int buf = kt & 1;
        if (kt + 1 < KT) {
            const int gk = (kt + 1) * GBK;
#pragma unroll
            for (int i = 0; i < 8; i++) {
                int idx = tid + i * 256;
                int ar = idx >> 4, ac = idx & 15;
                pa[i] = (bm + ar < M && gk + ac < K)
                            ? f2tf(A[(size_t)(bm + ar) * K + gk + ac]) : 0u;
                int bk = idx >> 7, bnn = idx & 127;
                pb[i] = (gk + bk < K) ? f2tf(B[(size_t)(gk + bk) * N + bn + bnn]) : 0u;
            }
        }
#pragma unroll
        for (int ks = 0; ks < 2; ks++) {
            const int kc = ks * 8;
            unsigned af[4][4], bf[4][2];
#pragma unroll
            for (int mf = 0; mf < 4; mf++) {
                int r = wm * 64 + mf * 16;
                af[mf][0] = As[buf][r + g][kc + tig];
                af[mf][1] = As[buf][r + g + 8][kc + tig];
                af[mf][2] = As[buf][r + g][kc + tig + 4];
                af[mf][3] = As[buf][r + g + 8][kc + tig + 4];
            }
#pragma unroll
            for (int nf = 0; nf < 4; nf++) {
                int c = wn * 32 + nf * 8 + g;
                bf[nf][0] = Bs[buf][c][kc + tig];
                bf[nf][1] = Bs[buf][c][kc + tig + 4];
            }
#pragma unroll
            for (int mf = 0; mf < 4; mf++)
#pragma unroll
                for (int nf = 0; nf < 4; nf++) {
                    asm volatile(
                        "mma.sync.aligned.m16n8k8.row.col.f32.tf32.tf32.f32 "
                        "{%0,%1,%2,%3}, {%4,%5,%6,%7}, {%8,%9}, {%0,%1,%2,%3};"
                        : "+f"(acc[mf][nf][0]), "+f"(acc[mf][nf][1]),
                          "+f"(acc[mf][nf][2]), "+f"(acc[mf][nf][3])
                        : "r"(af[mf][0]), "r"(af[mf][1]), "r"(af[mf][2]), "r"(af[mf][3]),
                          "r"(bf[nf][0]), "r"(bf[nf][1]));
                }
        }
        __syncthreads();
        if (kt + 1 < KT) {
#pragma unroll
            for (int i = 0; i < 8; i++) {
                int idx = tid + i * 256;
                As[buf ^ 1][idx >> 4][idx & 15] = pa[i];
                Bs[buf ^ 1][idx & 127][idx >> 7] = pb[i];
            }
            __syncthreads();
        }
    }

#pragma unroll
    for (int mf = 0; mf < 4; mf++) {
        int r0 = bm + wm * 64 + mf * 16 + g;
#pragma unroll
        for (int nf = 0; nf < 4; nf++) {
            int c0 = bn + wn * 32 + nf * 8 + tig * 2;
            if (r0 < M) {
                float2 v = make_float2(acc[mf][nf][0], acc[mf][nf][1]);
                *(float2*)(C + (size_t)r0 * N + c0) = v;
            }
            if (r0 + 8 < M) {
                float2 v = make_float2(acc[mf][nf][2], acc[mf][nf][3]);
                *(float2*)(C + (size_t)(r0 + 8) * N + c0) = v;
            }
        }
    }
}

// ---------------- attention scores per node ----------------------------------
__global__ void score_k(int N, int H, int F, int ld, int hs, int astride,
                        const float* __restrict__ Wh, const float* __restrict__ a,
                        float* __restrict__ ssrc, float* __restrict__ sdst) {
    int gw = (blockIdx.x * blockDim.x + threadIdx.x) >> 5;
    int lane = threadIdx.x & 31;
    if (gw >= N * H) return;
    int n = gw / H, h = gw - n * H;
    const float* row = Wh + (size_t)n * ld + h * hs;
    const float* av = a + (size_t)h * astride;
    float s1 = 0.f, s2 = 0.f;
    for (int f = lane; f < F; f += 32) {
        float v = row[f];
        s1 += v * av[f];
        s2 += v * av[F + f];
    }
#pragma unroll
    for (int o = 16; o; o >>= 1) {
        s1 += __shfl_xor_sync(0xffffffffu, s1, o);
        s2 += __shfl_xor_sync(0xffffffffu, s2, o);
    }
    if (lane == 0) {
        ssrc[h * N + n] = s1;
        sdst[h * N + n] = s2;
    }
}

// ---------------- fused softmax + gather aggregation --------------------------
// one warp per (dst, head). F4 = float4s per lane (1 or 2).
__global__ void agg_k(int N, int H, int F4, int ld, int hs, int outld, int ouths,
                      const int* __restrict__ rowptr, const int* __restrict__ csrSrc,
                      const float* __restrict__ ssrc, const float* __restrict__ sdst,
                      const float* __restrict__ Wh, float* __restrict__ out) {
    int gw = (blockIdx.x * blockDim.x + threadIdx.x) >> 5;
    if (gw >= N * H) return;
    int lane = threadIdx.x & 31;
    int d = gw / H, h = gw - d * H;
    int start = rowptr[d], end = rowptr[d + 1];
    float sd = sdst[h * N + d];
    const float* ss = ssrc + (size_t)h * N;

    // pass 1: max over incoming edges
    float m = -1e30f;
    for (int i = start + lane; i < end; i += 32)
        m = fmaxf(m, lrelu(ss[csrSrc[i]] + sd));
#pragma unroll
    for (int o = 16; o; o >>= 1) m = fmaxf(m, __shfl_xor_sync(0xffffffffu, m, o));

    // pass 1b: sum of exp
    float sum = 0.f;
    for (int i = start + lane; i < end; i += 32)
        sum += __expf(lrelu(ss[csrSrc[i]] + sd) - m);
#pragma unroll
    for (int o = 16; o; o >>= 1) sum += __shfl_xor_sync(0xffffffffu, sum, o);
    float inv = 1.f / (sum + 1e-16f);

    // pass 2: weighted gather of Wh[src] rows
    float4 a0 = make_float4(0.f, 0.f, 0.f, 0.f);
    float4 a1 = make_float4(0.f, 0.f, 0.f, 0.f);
#pragma unroll 2
    for (int i = start; i < end; i++) {
        int s = csrSrc[i];                       // warp-uniform broadcast load
        float w = __expf(lrelu(ss[s] + sd) - m) * inv;
        const float4* rp = (const float4*)(Wh + (size_t)s * ld + h * hs);
        float4 u = rp[lane];
        a0.x += w * u.x; a0.y += w * u.y; a0.z += w * u.z; a0.w += w * u.w;
        if (F4 == 2) {
            float4 u2 = rp[lane + 32];
            a1.x += w * u2.x; a1.y += w * u2.y; a1.z += w * u2.z; a1.w += w * u2.w;
        }
    }
    float4* op = (float4*)(out + (size_t)d * outld + h * ouths);
    op[lane] = a0;
    if (F4 == 2) op[lane + 32] = a1;
}

// ---------------- epilogues ---------------------------------------------------
__global__ void epi1_k(const float* __restrict__ h, float* __restrict__ x1, size_t cnt) {
    size_t i = (size_t)blockIdx.x * blockDim.x + threadIdx.x;
    if (i < cnt) x1[i] = eluf(eluf(h[i]));
}
__global__ void epi2_k(const float* __restrict__ h, const float* __restrict__ x1,
                       float* __restrict__ x2, size_t cnt) {
    size_t i = (size_t)blockIdx.x * blockDim.x + threadIdx.x;
    if (i < cnt) x2[i] = eluf(eluf(h[i]) + x1[i]);
}
// mean over 6 heads stored at (n, h, 128), then sigmoid
__global__ void final_k(const float* __restrict__ h3, float* __restrict__ out, int N) {
    int i = blockIdx.x * blockDim.x + threadIdx.x;
    if (i >= N * 121) return;
    int n = i / 121, f = i - n * 121;
    const float* base = h3 + (size_t)n * 768 + f;
    float v = 0.f;
#pragma unroll
    for (int h = 0; h < 6; h++) v += base[h * 128];
    v *= (1.f / 6.f);
    out[i] = 1.f / (1.f + __expf(-v));
}

// ---------------- driver ------------------------------------------------------
extern "C" void kernel_launch(void* const* d_in, const int* in_sizes, int n_in,
                              void* d_out, int out_size) {
    const float* x = (const float*)d_in[0];
    const void* ei = d_in[1];
    const float* W1 = (const float*)d_in[2];
    const float* a1 = (const float*)d_in[3];
    const float* W2 = (const float*)d_in[4];
    const float* a2 = (const float*)d_in[5];
    const float* W3 = (const float*)d_in[6];
    const float* a3 = (const float*)d_in[7];
    float* out = (float*)d_out;

    float *B, *Wh, *x1, *x2, *hb, *ssrc, *sdst;
    int *srcI, *dstI, *cnt, *rowptr, *cursor, *csrSrc;
    cudaGetSymbolAddress((void**)&B, g_B);
    cudaGetSymbolAddress((void**)&Wh, g_Wh);
    cudaGetSymbolAddress((void**)&x1, g_x1);
    cudaGetSymbolAddress((void**)&x2, g_x2);
    cudaGetSymbolAddress((void**)&hb, g_h);
    cudaGetSymbolAddress((void**)&ssrc, g_ssrc);
    cudaGetSymbolAddress((void**)&sdst, g_sdst);
    cudaGetSymbolAddress((void**)&srcI, g_srcI);
    cudaGetSymbolAddress((void**)&dstI, g_dstI);
    cudaGetSymbolAddress((void**)&cnt, g_cnt);
    cudaGetSymbolAddress((void**)&rowptr, g_rowptr);
    cudaGetSymbolAddress((void**)&cursor, g_cursor);
    cudaGetSymbolAddress((void**)&csrSrc, g_csrSrc);

    const int N = NN, E = NE;
    const int TB = 256;

    detect_k<<<1, 1>>>(ei, N);
    conv_edges<<<(E + TB - 1) / TB, TB>>>(ei, srcI, dstI, E);
    zero_i<<<(N + TB - 1) / TB, TB>>>(cnt, N);
    hist_k<<<(E + TB - 1) / TB, TB>>>(dstI, cnt, E);
    scan_k<<<1, 1024>>>(cnt, rowptr, N);
    copy_i<<<(N + TB - 1) / TB, TB>>>(rowptr, cursor, N);
    fill_k<<<(E + TB - 1) / TB, TB>>>(srcI, dstI, cursor, csrSrc, E);

    // ============ Layer 1: K=50, H=4, F=256 ============
    {
        int K = 50, H = 4, F = 256, FP = 256, Ntot = 1024;
        repack_w<<<(K * H * FP + TB - 1) / TB, TB>>>(W1, B, K, H, F, FP);
        dim3 g(Ntot / GBN, (N + GBM - 1) / GBM);
        gemm_tf32<<<g, 256>>>(N, Ntot, K, x, B, Wh);
        score_k<<<(N * H * 32 + TB - 1) / TB, TB>>>(N, H, F, Ntot, F, 2 * F, Wh, a1, ssrc, sdst);
        agg_k<<<((size_t)N * H * 32 + TB - 1) / TB, TB>>>(N, H, 2, Ntot, F, Ntot, F,
                                                          rowptr, csrSrc, ssrc, sdst, Wh, hb);
        epi1_k<<<((size_t)N * Ntot + TB - 1) / TB, TB>>>(hb, x1, (size_t)N * Ntot);
    }

    // ============ Layer 2: K=1024, H=4, F=256, skip ============
    {
        int K = 1024, H = 4, F = 256, FP = 256, Ntot = 1024;
        repack_w<<<(K * H * FP + TB - 1) / TB, TB>>>(W2, B, K, H, F, FP);
        dim3 g(Ntot / GBN, (N + GBM - 1) / GBM);
        gemm_tf32<<<g, 256>>>(N, Ntot, K, x1, B, Wh);
        score_k<<<(N * H * 32 + TB - 1) / TB, TB>>>(N, H, F, Ntot, F, 2 * F, Wh, a2, ssrc, sdst);
        agg_k<<<((size_t)N * H * 32 + TB - 1) / TB, TB>>>(N, H, 2, Ntot, F, Ntot, F,
                                                          rowptr, csrSrc, ssrc, sdst, Wh, hb);
        epi2_k<<<((size_t)N * Ntot + TB - 1) / TB, TB>>>(hb, x1, x2, (size_t)N * Ntot);
    }

    // ============ Layer 3: K=1024, H=6, F=121 (pad 128), mean heads ============
    {
        int K = 1024, H = 6, F = 121, FP = 128, Ntot = 768;
        repack_w<<<(K * H * FP + TB - 1) / TB, TB>>>(W3, B, K, H, F, FP);
        dim3 g(Ntot / GBN, (N + GBM - 1) / GBM);
        gemm_tf32<<<g, 256>>>(N, Ntot, K, x2, B, Wh);
        score_k<<<(N * H * 32 + TB - 1) / TB, TB>>>(N, H, F, Ntot, FP, 2 * F, Wh, a3, ssrc, sdst);
        // per-head disjoint output slices (n, h, 128); padded Wh cols are zero
        agg_k<<<((size_t)N * H * 32 + TB - 1) / TB, TB>>>(N, H, 1, Ntot, FP, Ntot, FP,
                                                          rowptr, csrSrc, ssrc, sdst, Wh, hb);
        final_k<<<(N * 121 + TB - 1) / TB, TB>>>(hb, out, N);
    }
}

// round 8
// speedup vs baseline: 5.0383x; 2.2035x over previous
#include <cuda_runtime.h>
#include <cstdint>
#include <cstddef>

#define NN 20000
#define NE 320000
#define ALPHA 0.2f

// ---------------- scratch (device globals; no allocation allowed) ------------
__device__ __align__(16) float g_B[1024 * 1024];
__device__ __align__(16) float g_Wh[(size_t)NN * 1024];
__device__ __align__(16) float g_x1[(size_t)NN * 1024];
__device__ __align__(16) float g_x2[(size_t)NN * 1024];
__device__ __align__(16) float g_h[(size_t)NN * 1024];
__device__ __align__(16) float g_xp[(size_t)NN * 64];     // padded layer-1 input
__device__ __align__(16) float g_ssrc[6 * NN];
__device__ __align__(16) float g_sdst[6 * NN];
__device__ __align__(16) int g_srcI[NE];
__device__ __align__(16) int g_dstI[NE];
__device__ __align__(16) int g_cnt[NN];
__device__ __align__(16) int g_rowptr[NN + 4];
__device__ __align__(16) int g_cursor[NN];
__device__ __align__(16) int g_csrSrc[NE];
__device__ int g_is64;

// ---------------- helpers ----------------------------------------------------
__device__ __forceinline__ float eluf(float z) {
    return z > 0.f ? z : expm1f(z);
}
__device__ __forceinline__ float lrelu(float v) {
    return v > 0.f ? v : ALPHA * v;
}
__device__ __forceinline__ unsigned smem_u32(const void* p) {
    return (unsigned)__cvta_generic_to_shared(p);
}
__device__ __forceinline__ void cp16(unsigned dst, const void* src, int szbytes) {
    asm volatile("cp.async.cg.shared.global [%0], [%1], 16, %2;"
                 :: "r"(dst), "l"(src), "r"(szbytes));
}
__device__ __forceinline__ void cp_commit() {
    asm volatile("cp.async.commit_group;");
}
template <int NWAIT>
__device__ __forceinline__ void cp_wait() {
    asm volatile("cp.async.wait_group %0;" :: "n"(NWAIT));
}

// ---------------- edge index dtype probe + conversion -------------------------
__global__ void detect_k(const void* __restrict__ ei, int N) {
    const long long* p = (const long long*)ei;
    int ok64 = 1;
    for (int i = 0; i < 1024; i++) {
        long long v = p[i];
        if (v < 0 || v >= N) { ok64 = 0; break; }
    }
    g_is64 = ok64;
}

__global__ void conv_edges(const void* __restrict__ ei, int* __restrict__ s,
                           int* __restrict__ d, int E) {
    int i = blockIdx.x * blockDim.x + threadIdx.x;
    if (i >= E) return;
    if (g_is64) {
        const long long* p = (const long long*)ei;
        s[i] = (int)p[i];
        d[i] = (int)p[E + i];
    } else {
        const int* p = (const int*)ei;
        s[i] = p[i];
        d[i] = p[E + i];
    }
}

// ---------------- CSR build ---------------------------------------------------
__global__ void zero_i(int* p, int n) {
    int i = blockIdx.x * blockDim.x + threadIdx.x;
    if (i < n) p[i] = 0;
}
__global__ void hist_k(const int* __restrict__ dst, int* __restrict__ cnt, int E) {
    int i = blockIdx.x * blockDim.x + threadIdx.x;
    if (i < E) atomicAdd(&cnt[dst[i]], 1);
}
__global__ void scan_k(const int* __restrict__ cnt, int* __restrict__ rowptr, int n) {
    __shared__ int sh[1024];
    __shared__ int carry;
    int t = threadIdx.x;
    if (t == 0) { carry = 0; rowptr[0] = 0; }
    __syncthreads();
    for (int base = 0; base < n; base += 1024) {
        int v = (base + t < n) ? cnt[base + t] : 0;
        sh[t] = v;
        __syncthreads();
        for (int o = 1; o < 1024; o <<= 1) {
            int x = (t >= o) ? sh[t - o] : 0;
            __syncthreads();
            sh[t] += x;
            __syncthreads();
        }
        if (base + t < n) rowptr[base + t + 1] = sh[t] + carry;
        __syncthreads();
        if (t == 0) carry += sh[1023];
        __syncthreads();
    }
}
__global__ void copy_i(const int* __restrict__ a, int* __restrict__ b, int n) {
    int i = blockIdx.x * blockDim.x + threadIdx.x;
    if (i < n) b[i] = a[i];
}
__global__ void fill_k(const int* __restrict__ src, const int* __restrict__ dst,
                       int* __restrict__ cursor, int* __restrict__ csrSrc, int E) {
    int i = blockIdx.x * blockDim.x + threadIdx.x;
    if (i >= E) return;
    int pos = atomicAdd(&cursor[dst[i]], 1);
    csrSrc[pos] = src[i];
}

// ---------------- input pad: x (N,50) -> xp (N,64) ----------------------------
__global__ void pad_x(const float* __restrict__ x, float* __restrict__ xp, int N) {
    int i = blockIdx.x * blockDim.x + threadIdx.x;
    if (i >= N * 64) return;
    int n = i >> 6, c = i & 63;
    xp[i] = (c < 50) ? x[n * 50 + c] : 0.f;
}

// ---------------- repack: W (H,K,F) -> B (Kp, H*FP), zero pad -----------------
__global__ void repack_w(const float* __restrict__ W, float* __restrict__ B,
                         int K, int Kp, int H, int F, int FP) {
    int total = Kp * H * FP;
    int idx = blockIdx.x * blockDim.x + threadIdx.x;
    if (idx >= total) return;
    int hf = H * FP;
    int k = idx / hf;
    int rem = idx - k * hf;
    int h = rem / FP;
    int f = rem - h * FP;
    B[idx] = (k < K && f < F) ? W[((size_t)h * K + k) * F + f] : 0.f;
}

// ---------------- TF32 tensor-core GEMM with cp.async -------------------------
// C[M,N] = A[M,K] * B[K,N]; K multiple of 16, N multiple of 128, A rows 16B-aligned.
// Raw fp32 bits fed to mma.tf32 (hardware truncates mantissa).
#define GBM 128
#define GBN 128
#define GBK 16
#define APAD 20    // As row stride (words); 80B = 5*16 -> cp.async-aligned
#define BPAD 136   // Bs row stride (words); 544B aligned; tig*8 banks -> conflict-free

__global__ __launch_bounds__(256) void gemm_tf32(int M, int N, int K,
                                                 const float* __restrict__ A,
                                                 const float* __restrict__ B,
                                                 float* __restrict__ C) {
    __shared__ float As[2][GBM][APAD];   // [row][k]
    __shared__ float Bs[2][GBK][BPAD];   // [k][n]

    const int tid = threadIdx.x;
    const int warp = tid >> 5;
    const int lane = tid & 31;
    const int g = lane >> 2;
    const int tig = lane & 3;
    const int wm = warp & 1;
    const int wn = warp >> 1;
    const int bm = blockIdx.y * GBM;
    const int bn = blockIdx.x * GBN;

    // per-thread copy coordinates
    const int ar0 = tid >> 2, ac0 = (tid & 3) * 4;        // A chunk 0: 64 rows span
    const int ar1 = (tid + 256) >> 2, ac1 = ac0;          // A chunk 1
    const int bk0 = tid >> 5, bc0 = (tid & 31) * 4;       // B chunk 0: rows 0..7
    const int bk1 = (tid + 256) >> 5, bc1 = bc0;          // B chunk 1: rows 8..15

    float acc[4][4][4];
#pragma unroll
    for (int mf = 0; mf < 4; mf++)
#pragma unroll
        for (int nf = 0; nf < 4; nf++)
#pragma unroll
            for (int r = 0; r < 4; r++) acc[mf][nf][r] = 0.f;

    const int KT = K / GBK;

    auto issue = [&](int kt, int buf) {
        const int k0 = kt * GBK;
        cp16(smem_u32(&As[buf][ar0][ac0]), A + (size_t)(bm + ar0) * K + k0 + ac0,
             (bm + ar0 < M) ? 16 : 0);
        cp16(smem_u32(&As[buf][ar1][ac1]), A + (size_t)(bm + ar1) * K + k0 + ac1,
             (bm + ar1 < M) ? 16 : 0);
        cp16(smem_u32(&Bs[buf][bk0][bc0]), B + (size_t)(k0 + bk0) * N + bn + bc0, 16);
        cp16(smem_u32(&Bs[buf][bk1][bc1]), B + (size_t)(k0 + bk1) * N + bn + bc1, 16);
    };

    issue(0, 0);
    cp_commit();

    for (int kt = 0; kt < KT; kt++) {
        const int buf = kt & 1;
        if (kt + 1 < KT) {
            issue(kt + 1, buf ^ 1);
            cp_commit();
            cp_wait<1>();
        } else {
            cp_wait<0>();
        }
        __syncthreads();

#pragma unroll
        for (int ks = 0; ks < 2; ks++) {
            const int kc = ks * 8;
            unsigned af[4][4], bf[4][2];
#pragma unroll
            for (int mf = 0; mf < 4; mf++) {
                int r = wm * 64 + mf * 16;
                af[mf][0] = __float_as_uint(As[buf][r + g][kc + tig]);
                af[mf][1] = __float_as_uint(As[buf][r + g + 8][kc + tig]);
                af[mf][2] = __float_as_uint(As[buf][r + g][kc + tig + 4]);
                af[mf][3] = __float_as_uint(As[buf][r + g + 8][kc + tig + 4]);
            }
#pragma unroll
            for (int nf = 0; nf < 4; nf++) {
                int c = wn * 32 + nf * 8 + g;
                bf[nf][0] = __float_as_uint(Bs[buf][kc + tig][c]);
                bf[nf][1] = __float_as_uint(Bs[buf][kc + tig + 4][c]);
            }
#pragma unroll
            for (int mf = 0; mf < 4; mf++)
#pragma unroll
                for (int nf = 0; nf < 4; nf++) {
                    asm volatile(
                        "mma.sync.aligned.m16n8k8.row.col.f32.tf32.tf32.f32 "
                        "{%0,%1,%2,%3}, {%4,%5,%6,%7}, {%8,%9}, {%0,%1,%2,%3};"
                        : "+f"(acc[mf][nf][0]), "+f"(acc[mf][nf][1]),
                          "+f"(acc[mf][nf][2]), "+f"(acc[mf][nf][3])
                        : "r"(af[mf][0]), "r"(af[mf][1]), "r"(af[mf][2]), "r"(af[mf][3]),
                          "r"(bf[nf][0]), "r"(bf[nf][1]));
                }
        }
        __syncthreads();
    }

#pragma unroll
    for (int mf = 0; mf < 4; mf++) {
        int r0 = bm + wm * 64 + mf * 16 + g;
#pragma unroll
        for (int nf = 0; nf < 4; nf++) {
            int c0 = bn + wn * 32 + nf * 8 + tig * 2;
            if (r0 < M) {
                float2 v = make_float2(acc[mf][nf][0], acc[mf][nf][1]);
                *(float2*)(C + (size_t)r0 * N + c0) = v;
            }
            if (r0 + 8 < M) {
                float2 v = make_float2(acc[mf][nf][2], acc[mf][nf][3]);
                *(float2*)(C + (size_t)(r0 + 8) * N + c0) = v;
            }
        }
    }
}

// ---------------- attention scores per node ----------------------------------
__global__ void score_k(int N, int H, int F, int ld, int hs, int astride,
                        const float* __restrict__ Wh, const float* __restrict__ a,
                        float* __restrict__ ssrc, float* __restrict__ sdst) {
    int gw = (blockIdx.x * blockDim.x + threadIdx.x) >> 5;
    int lane = threadIdx.x & 31;
    if (gw >= N * H) return;
    int n = gw / H, h = gw - n * H;
    const float* row = Wh + (size_t)n * ld + h * hs;
    const float* av = a + (size_t)h * astride;
    float s1 = 0.f, s2 = 0.f;
    for (int f = lane; f < F; f += 32) {
        float v = row[f];
        s1 += v * av[f];
        s2 += v * av[F + f];
    }
#pragma unroll
    for (int o = 16; o; o >>= 1) {
        s1 += __shfl_xor_sync(0xffffffffu, s1, o);
        s2 += __shfl_xor_sync(0xffffffffu, s2, o);
    }
    if (lane == 0) {
        ssrc[h * N + n] = s1;
        sdst[h * N + n] = s2;
    }
}

// ---------------- fused softmax + gather aggregation + epilogue ---------------
// one warp per (dst, head). F4 = float4s per lane (1 or 2).
// mode 0: raw store; 1: elu(elu(v)); 2: elu(elu(v) + x1)
__global__ void agg_k(int N, int H, int F4, int ld, int hs, int outld, int ouths,
                      int mode,
                      const int* __restrict__ rowptr, const int* __restrict__ csrSrc,
                      const float* __restrict__ ssrc, const float* __restrict__ sdst,
                      const float* __restrict__ Wh, const float* __restrict__ xskip,
                      float* __restrict__ out) {
    int gw = (blockIdx.x * blockDim.x + threadIdx.x) >> 5;
    if (gw >= N * H) return;
    int lane = threadIdx.x & 31;
    int d = gw / H, h = gw - d * H;
    int start = rowptr[d], end = rowptr[d + 1];
    float sd = sdst[h * N + d];
    const float* ss = ssrc + (size_t)h * N;

    float m = -1e30f;
    for (int i = start + lane; i < end; i += 32)
        m = fmaxf(m, lrelu(ss[csrSrc[i]] + sd));
#pragma unroll
    for (int o = 16; o; o >>= 1) m = fmaxf(m, __shfl_xor_sync(0xffffffffu, m, o));

    float sum = 0.f;
    for (int i = start + lane; i < end; i += 32)
        sum += __expf(lrelu(ss[csrSrc[i]] + sd) - m);
#pragma unroll
    for (int o = 16; o; o >>= 1) sum += __shfl_xor_sync(0xffffffffu, sum, o);
    float inv = 1.f / (sum + 1e-16f);

    float4 a0 = make_float4(0.f, 0.f, 0.f, 0.f);
    float4 a1 = make_float4(0.f, 0.f, 0.f, 0.f);
#pragma unroll 2
    for (int i = start; i < end; i++) {
        int s = csrSrc[i];
        float w = __expf(lrelu(ss[s] + sd) - m) * inv;
        const float4* rp = (const float4*)(Wh + (size_t)s * ld + h * hs);
        float4 u = rp[lane];
        a0.x += w * u.x; a0.y += w * u.y; a0.z += w * u.z; a0.w += w * u.w;
        if (F4 == 2) {
            float4 u2 = rp[lane + 32];
            a1.x += w * u2.x; a1.y += w * u2.y; a1.z += w * u2.z; a1.w += w * u2.w;
        }
    }

    size_t obase = (size_t)d * outld + h * ouths;
    if (mode == 1) {
        a0.x = eluf(eluf(a0.x)); a0.y = eluf(eluf(a0.y));
        a0.z = eluf(eluf(a0.z)); a0.w = eluf(eluf(a0.w));
        a1.x = eluf(eluf(a1.x)); a1.y = eluf(eluf(a1.y));
        a1.z = eluf(eluf(a1.z)); a1.w = eluf(eluf(a1.w));
    } else if (mode == 2) {
        const float4* xp = (const float4*)(xskip + obase);
        float4 p0 = xp[lane];
        a0.x = eluf(eluf(a0.x) + p0.x); a0.y = eluf(eluf(a0.y) + p0.y);
        a0.z = eluf(eluf(a0.z) + p0.z); a0.w = eluf(eluf(a0.w) + p0.w);
        if (F4 == 2) {
            float4 p1 = xp[lane + 32];
            a1.x = eluf(eluf(a1.x) + p1.x); a1.y = eluf(eluf(a1.y) + p1.y);
            a1.z = eluf(eluf(a1.z) + p1.z); a1.w = eluf(eluf(a1.w) + p1.w);
        }
    }
    float4* op = (float4*)(out + obase);
    op[lane] = a0;
    if (F4 == 2) op[lane + 32] = a1;
}

// ---------------- final: mean over 6 heads + sigmoid --------------------------
__global__ void final_k(const float* __restrict__ h3, float* __restrict__ out, int N) {
    int i = blockIdx.x * blockDim.x + threadIdx.x;
    if (i >= N * 121) return;
    int n = i / 121, f = i - n * 121;
    const float* base = h3 + (size_t)n * 768 + f;
    float v = 0.f;
#pragma unroll
    for (int h = 0; h < 6; h++) v += base[h * 128];
    v *= (1.f / 6.f);
    out[i] = 1.f / (1.f + __expf(-v));
}

// ---------------- driver ------------------------------------------------------
extern "C" void kernel_launch(void* const* d_in, const int* in_sizes, int n_in,
                              void* d_out, int out_size) {
    const float* x = (const float*)d_in[0];
    const void* ei = d_in[1];
    const float* W1 = (const float*)d_in[2];
    const float* a1 = (const float*)d_in[3];
    const float* W2 = (const float*)d_in[4];
    const float* a2 = (const float*)d_in[5];
    const float* W3 = (const float*)d_in[6];
    const float* a3 = (const float*)d_in[7];
    float* out = (float*)d_out;

    float *B, *Wh, *x1, *x2, *hb, *xp, *ssrc, *sdst;
    int *srcI, *dstI, *cnt, *rowptr, *cursor, *csrSrc;
    cudaGetSymbolAddress((void**)&B, g_B);
    cudaGetSymbolAddress((void**)&Wh, g_Wh);
    cudaGetSymbolAddress((void**)&x1, g_x1);
    cudaGetSymbolAddress((void**)&x2, g_x2);
    cudaGetSymbolAddress((void**)&hb, g_h);
    cudaGetSymbolAddress((void**)&xp, g_xp);
    cudaGetSymbolAddress((void**)&ssrc, g_ssrc);
    cudaGetSymbolAddress((void**)&sdst, g_sdst);
    cudaGetSymbolAddress((void**)&srcI, g_srcI);
    cudaGetSymbolAddress((void**)&dstI, g_dstI);
    cudaGetSymbolAddress((void**)&cnt, g_cnt);
    cudaGetSymbolAddress((void**)&rowptr, g_rowptr);
    cudaGetSymbolAddress((void**)&cursor, g_cursor);
    cudaGetSymbolAddress((void**)&csrSrc, g_csrSrc);

    const int N = NN, E = NE;
    const int TB = 256;

    detect_k<<<1, 1>>>(ei, N);
    conv_edges<<<(E + TB - 1) / TB, TB>>>(ei, srcI, dstI, E);
    zero_i<<<(N + TB - 1) / TB, TB>>>(cnt, N);
    hist_k<<<(E + TB - 1) / TB, TB>>>(dstI, cnt, E);
    scan_k<<<1, 1024>>>(cnt, rowptr, N);
    copy_i<<<(N + TB - 1) / TB, TB>>>(rowptr, cursor, N);
    fill_k<<<(E + TB - 1) / TB, TB>>>(srcI, dstI, cursor, csrSrc, E);
    pad_x<<<(N * 64 + TB - 1) / TB, TB>>>(x, xp, N);

    // ============ Layer 1: K=50->64, H=4, F=256 ============
    {
        int K = 50, Kp = 64, H = 4, F = 256, FP = 256, Ntot = 1024;
        repack_w<<<(Kp * H * FP + TB - 1) / TB, TB>>>(W1, B, K, Kp, H, F, FP);
        dim3 g(Ntot / GBN, (N + GBM - 1) / GBM);
        gemm_tf32<<<g, 256>>>(N, Ntot, Kp, xp, B, Wh);
        score_k<<<(N * H * 32 + TB - 1) / TB, TB>>>(N, H, F, Ntot, F, 2 * F, Wh, a1, ssrc, sdst);
        agg_k<<<((size_t)N * H * 32 + TB - 1) / TB, TB>>>(N, H, 2, Ntot, F, Ntot, F, 1,
                                                          rowptr, csrSrc, ssrc, sdst, Wh,
                                                          nullptr, x1);
    }

    // ============ Layer 2: K=1024, H=4, F=256, skip ============
    {
        int K = 1024, H = 4, F = 256, FP = 256, Ntot = 1024;
        repack_w<<<(K * H * FP + TB - 1) / TB, TB>>>(W2, B, K, K, H, F, FP);
        dim3 g(Ntot / GBN, (N + GBM - 1) / GBM);
        gemm_tf32<<<g, 256>>>(N, Ntot, K, x1, B, Wh);
        score_k<<<(N * H * 32 + TB - 1) / TB, TB>>>(N, H, F, Ntot, F, 2 * F, Wh, a2, ssrc, sdst);
        agg_k<<<((size_t)N * H * 32 + TB - 1) / TB, TB>>>(N, H, 2, Ntot, F, Ntot, F, 2,
                                                          rowptr, csrSrc, ssrc, sdst, Wh,
                                                          x1, x2);
    }

    // ============ Layer 3: K=1024, H=6, F=121 (pad 128), mean heads ============
    {
        int K = 1024, H = 6, F = 121, FP = 128, Ntot = 768;
        repack_w<<<(K * H * FP + TB - 1) / TB, TB>>>(W3, B, K, K, H, F, FP);
        dim3 g(Ntot / GBN, (N + GBM - 1) / GBM);
        gemm_tf32<<<g, 256>>>(N, Ntot, K, x2, B, Wh);
        score_k<<<(N * H * 32 + TB - 1) / TB, TB>>>(N, H, F, Ntot, FP, 2 * F, Wh, a3, ssrc, sdst);
        agg_k<<<((size_t)N * H * 32 + TB - 1) / TB, TB>>>(N, H, 1, Ntot, FP, Ntot, FP, 0,
                                                          rowptr, csrSrc, ssrc, sdst, Wh,
                                                          nullptr, hb);
        final_k<<<(N * 121 + TB - 1) / TB, TB>>>(hb, out, N);
    }
}

// round 9
// speedup vs baseline: 5.3304x; 1.0580x over previous
#include <cuda_runtime.h>
#include <cstdint>
#include <cstddef>

#define NN 20000
#define NE 320000
#define ALPHA 0.2f

// ---------------- scratch (device globals; no allocation allowed) ------------
__device__ __align__(16) float g_B[1024 * 1024];
__device__ __align__(16) float g_Wh[(size_t)NN * 1024];
__device__ __align__(16) float g_x1[(size_t)NN * 1024];
__device__ __align__(16) float g_x2[(size_t)NN * 1024];
__device__ __align__(16) float g_h[(size_t)NN * 1024];
__device__ __align__(16) float g_xp[(size_t)NN * 64];
__device__ __align__(16) float g_ssrc[6 * NN];
__device__ __align__(16) float g_sdst[6 * NN];
__device__ __align__(16) int g_srcI[NE];
__device__ __align__(16) int g_dstI[NE];
__device__ __align__(16) int g_cnt[NN];
__device__ __align__(16) int g_rowptr[NN + 4];
__device__ __align__(16) int g_cursor[NN];
__device__ __align__(16) int g_csrSrc[NE];
__device__ int g_is64;

// ---------------- helpers ----------------------------------------------------
__device__ __forceinline__ float eluf(float z) { return z > 0.f ? z : expm1f(z); }
__device__ __forceinline__ float lrelu(float v) { return v > 0.f ? v : ALPHA * v; }
__device__ __forceinline__ unsigned smem_u32(const void* p) {
    return (unsigned)__cvta_generic_to_shared(p);
}
__device__ __forceinline__ void cp16(unsigned dst, const void* src, int szbytes) {
    asm volatile("cp.async.cg.shared.global [%0], [%1], 16, %2;"
                 :: "r"(dst), "l"(src), "r"(szbytes));
}
__device__ __forceinline__ void cp_commit() { asm volatile("cp.async.commit_group;"); }
template <int NWAIT>
__device__ __forceinline__ void cp_wait() {
    asm volatile("cp.async.wait_group %0;" :: "n"(NWAIT));
}

// ---------------- setup kernels -----------------------------------------------
__global__ void detect_k(const void* __restrict__ ei, int N) {
    const long long* p = (const long long*)ei;
    int ok64 = 1;
    for (int i = 0; i < 1024; i++) {
        long long v = p[i];
        if (v < 0 || v >= N) { ok64 = 0; break; }
    }
    g_is64 = ok64;
}
__global__ void zero_i(int* p, int n) {
    int i = blockIdx.x * blockDim.x + threadIdx.x;
    if (i < n) p[i] = 0;
}
// convert + histogram fused
__global__ void convhist_k(const void* __restrict__ ei, int* __restrict__ s,
                           int* __restrict__ d, int* __restrict__ cnt, int E) {
    int i = blockIdx.x * blockDim.x + threadIdx.x;
    if (i >= E) return;
    int sv, dv;
    if (g_is64) {
        const long long* p = (const long long*)ei;
        sv = (int)p[i]; dv = (int)p[E + i];
    } else {
        const int* p = (const int*)ei;
        sv = p[i]; dv = p[E + i];
    }
    s[i] = sv; d[i] = dv;
    atomicAdd(&cnt[dv], 1);
}
// single-block scan; also seeds cursor
__global__ void scan_k(const int* __restrict__ cnt, int* __restrict__ rowptr,
                       int* __restrict__ cursor, int n) {
    __shared__ int sh[1024];
    __shared__ int carry;
    int t = threadIdx.x;
    if (t == 0) { carry = 0; rowptr[0] = 0; }
    __syncthreads();
    for (int base = 0; base < n; base += 1024) {
        int v = (base + t < n) ? cnt[base + t] : 0;
        int excl_in = carry;                      // carry before this block
        sh[t] = v;
        __syncthreads();
        for (int o = 1; o < 1024; o <<= 1) {
            int x = (t >= o) ? sh[t - o] : 0;
            __syncthreads();
            sh[t] += x;
            __syncthreads();
        }
        if (base + t < n) {
            int incl = sh[t] + excl_in;
            rowptr[base + t + 1] = incl;
            cursor[base + t] = incl - v;          // exclusive = start position
        }
        __syncthreads();
        if (t == 0) carry += sh[1023];
        __syncthreads();
    }
}
__global__ void fill_k(const int* __restrict__ src, const int* __restrict__ dst,
                       int* __restrict__ cursor, int* __restrict__ csrSrc, int E) {
    int i = blockIdx.x * blockDim.x + threadIdx.x;
    if (i >= E) return;
    int pos = atomicAdd(&cursor[dst[i]], 1);
    csrSrc[pos] = src[i];
}
__global__ void pad_x(const float* __restrict__ x, float* __restrict__ xp, int N) {
    int i = blockIdx.x * blockDim.x + threadIdx.x;
    if (i >= N * 64) return;
    int n = i >> 6, c = i & 63;
    xp[i] = (c < 50) ? x[n * 50 + c] : 0.f;
}
__global__ void zero2_k(float* a, float* b, int n) {
    int i = blockIdx.x * blockDim.x + threadIdx.x;
    if (i < n) { a[i] = 0.f; b[i] = 0.f; }
}
__global__ void repack_w(const float* __restrict__ W, float* __restrict__ B,
                         int K, int Kp, int H, int F, int FP) {
    int total = Kp * H * FP;
    int idx = blockIdx.x * blockDim.x + threadIdx.x;
    if (idx >= total) return;
    int hf = H * FP;
    int k = idx / hf;
    int rem = idx - k * hf;
    int h = rem / FP;
    int f = rem - h * FP;
    B[idx] = (k < K && f < F) ? W[((size_t)h * K + k) * F + f] : 0.f;
}

// ---------------- TF32 GEMM, 3-stage cp.async, fused attention scores ---------
// C[M,N] = A[M,K]*B[K,N]. Also: ssrc[h*NN+row] += dot(C_row_headslice, av[0:F]),
// sdst likewise with av[F:2F]. Each CTA's 128 cols lie in ONE head (128 | hs).
#define GBM 128
#define GBN 128
#define GBK 16
#define APAD 20
#define BPAD 136
#define AS_WORDS (GBM * APAD)              // 2560
#define BS_WORDS (GBK * BPAD)              // 2176
#define STAGE_WORDS (AS_WORDS + BS_WORDS)  // 4736 (18944 B, 16B-aligned)
#define GEMM_SMEM (3 * STAGE_WORDS * 4)    // 56832 B

__global__ __launch_bounds__(256) void gemm_tf32(int M, int N, int K,
                                                 const float* __restrict__ A,
                                                 const float* __restrict__ B,
                                                 float* __restrict__ C,
                                                 const float* __restrict__ aVec,
                                                 int F, int hs, int astride,
                                                 float* __restrict__ ssrc,
                                                 float* __restrict__ sdst) {
    extern __shared__ float sm[];

    const int tid = threadIdx.x;
    const int warp = tid >> 5;
    const int lane = tid & 31;
    const int g = lane >> 2;
    const int tig = lane & 3;
    const int wm = warp & 1;
    const int wn = warp >> 1;
    const int bm = blockIdx.y * GBM;
    const int bn = blockIdx.x * GBN;

    const int ar0 = tid >> 2, ac0 = (tid & 3) * 4;
    const int ar1 = (tid + 256) >> 2;
    const int bk0 = tid >> 5, bc0 = (tid & 31) * 4;
    const int bk1 = (tid + 256) >> 5;

    float acc[4][4][4];
#pragma unroll
    for (int mf = 0; mf < 4; mf++)
#pragma unroll
        for (int nf = 0; nf < 4; nf++)
#pragma unroll
            for (int r = 0; r < 4; r++) acc[mf][nf][r] = 0.f;

    const int KT = K / GBK;

    auto issue = [&](int kt, int stg) {
        float* As = sm + stg * STAGE_WORDS;
        float* Bs = As + AS_WORDS;
        const int k0 = kt * GBK;
        cp16(smem_u32(As + ar0 * APAD + ac0), A + (size_t)(bm + ar0) * K + k0 + ac0,
             (bm + ar0 < M) ? 16 : 0);
        cp16(smem_u32(As + ar1 * APAD + ac0), A + (size_t)(bm + ar1) * K + k0 + ac0,
             (bm + ar1 < M) ? 16 : 0);
        cp16(smem_u32(Bs + bk0 * BPAD + bc0), B + (size_t)(k0 + bk0) * N + bn + bc0, 16);
        cp16(smem_u32(Bs + bk1 * BPAD + bc0), B + (size_t)(k0 + bk1) * N + bn + bc0, 16);
    };

    issue(0, 0); cp_commit();
    if (KT > 1) issue(1, 1);
    cp_commit();

    int stg = 0, stg2 = (KT > 2) ? 2 : (KT == 2 ? 0 : 1);  // stage for kt+2
    for (int kt = 0; kt < KT; kt++) {
        cp_wait<1>();
        __syncthreads();
        if (kt + 2 < KT) issue(kt + 2, stg2);
        cp_commit();

        const float* As = sm + stg * STAGE_WORDS;
        const float* Bs = As + AS_WORDS;
#pragma unroll
        for (int ks = 0; ks < 2; ks++) {
            const int kc = ks * 8;
            unsigned af[4][4], bf[4][2];
#pragma unroll
            for (int mf = 0; mf < 4; mf++) {
                int r = wm * 64 + mf * 16;
                af[mf][0] = __float_as_uint(As[(r + g) * APAD + kc + tig]);
                af[mf][1] = __float_as_uint(As[(r + g + 8) * APAD + kc + tig]);
                af[mf][2] = __float_as_uint(As[(r + g) * APAD + kc + tig + 4]);
                af[mf][3] = __float_as_uint(As[(r + g + 8) * APAD + kc + tig + 4]);
            }
#pragma unroll
            for (int nf = 0; nf < 4; nf++) {
                int c = wn * 32 + nf * 8 + g;
                bf[nf][0] = __float_as_uint(Bs[(kc + tig) * BPAD + c]);
                bf[nf][1] = __float_as_uint(Bs[(kc + tig + 4) * BPAD + c]);
            }
#pragma unroll
            for (int mf = 0; mf < 4; mf++)
#pragma unroll
                for (int nf = 0; nf < 4; nf++) {
                    asm volatile(
                        "mma.sync.aligned.m16n8k8.row.col.f32.tf32.tf32.f32 "
                        "{%0,%1,%2,%3}, {%4,%5,%6,%7}, {%8,%9}, {%0,%1,%2,%3};"
                        : "+f"(acc[mf][nf][0]), "+f"(acc[mf][nf][1]),
                          "+f"(acc[mf][nf][2]), "+f"(acc[mf][nf][3])
                        : "r"(af[mf][0]), "r"(af[mf][1]), "r"(af[mf][2]), "r"(af[mf][3]),
                          "r"(bf[nf][0]), "r"(bf[nf][1]));
                }
        }
        stg = (stg + 1 == 3) ? 0 : stg + 1;
        stg2 = (stg2 + 1 == 3) ? 0 : stg2 + 1;
    }

    // ---- store C ----
#pragma unroll
    for (int mf = 0; mf < 4; mf++) {
        int r0 = bm + wm * 64 + mf * 16 + g;
#pragma unroll
        for (int nf = 0; nf < 4; nf++) {
            int c0 = bn + wn * 32 + nf * 8 + tig * 2;
            if (r0 < M) {
                float2 v = make_float2(acc[mf][nf][0], acc[mf][nf][1]);
                *(float2*)(C + (size_t)r0 * N + c0) = v;
            }
            if (r0 + 8 < M) {
                float2 v = make_float2(acc[mf][nf][2], acc[mf][nf][3]);
                *(float2*)(C + (size_t)(r0 + 8) * N + c0) = v;
            }
        }
    }

    // ---- fused attention-score partial dot:  per-row acc · a-slice ----
    {
        const int h0 = bn / hs;             // head of this CTA's col slice
        const int cbase = bn % hs;          // col offset within head
        const float* av = aVec + (size_t)h0 * astride;
        float as_[8], ad_[8];
#pragma unroll
        for (int nf = 0; nf < 4; nf++)
#pragma unroll
            for (int e = 0; e < 2; e++) {
                int cf = cbase + wn * 32 + nf * 8 + tig * 2 + e;
                bool ok = cf < F;
                as_[nf * 2 + e] = ok ? av[cf] : 0.f;
                ad_[nf * 2 + e] = ok ? av[F + cf] : 0.f;
            }
#pragma unroll
        for (int mf = 0; mf < 4; mf++) {
            float s0 = 0.f, d0 = 0.f, s1 = 0.f, d1 = 0.f;
#pragma unroll
            for (int nf = 0; nf < 4; nf++)
#pragma unroll
                for (int e = 0; e < 2; e++) {
                    int idx = nf * 2 + e;
                    s0 += acc[mf][nf][e] * as_[idx];
                    d0 += acc[mf][nf][e] * ad_[idx];
                    s1 += acc[mf][nf][2 + e] * as_[idx];
                    d1 += acc[mf][nf][2 + e] * ad_[idx];
                }
#pragma unroll
            for (int o = 1; o <= 2; o <<= 1) {
                s0 += __shfl_xor_sync(0xffffffffu, s0, o);
                d0 += __shfl_xor_sync(0xffffffffu, d0, o);
                s1 += __shfl_xor_sync(0xffffffffu, s1, o);
                d1 += __shfl_xor_sync(0xffffffffu, d1, o);
            }
            if (tig == 0) {
                int r0 = bm + wm * 64 + mf * 16 + g;
                if (r0 < M) {
                    atomicAdd(&ssrc[h0 * NN + r0], s0);
                    atomicAdd(&sdst[h0 * NN + r0], d0);
                }
                if (r0 + 8 < M) {
                    atomicAdd(&ssrc[h0 * NN + r0 + 8], s1);
                    atomicAdd(&sdst[h0 * NN + r0 + 8], d1);
                }
            }
        }
    }
}

// ---------------- fused softmax + gather aggregation + epilogue ---------------
__global__ void agg_k(int N, int H, int F4, int ld, int hs, int outld, int ouths,
                      int mode,
                      const int* __restrict__ rowptr, const int* __restrict__ csrSrc,
                      const float* __restrict__ ssrc, const float* __restrict__ sdst,
                      const float* __restrict__ Wh, const float* __restrict__ xskip,
                      float* __restrict__ out) {
    int gw = (blockIdx.x * blockDim.x + threadIdx.x) >> 5;
    if (gw >= N * H) return;
    int lane = threadIdx.x & 31;
    int d = gw / H, h = gw - d * H;
    int start = rowptr[d], end = rowptr[d + 1];
    float sd = sdst[h * N + d];
    const float* ss = ssrc + (size_t)h * N;

    float m = -1e30f;
    for (int i = start + lane; i < end; i += 32)
        m = fmaxf(m, lrelu(ss[csrSrc[i]] + sd));
#pragma unroll
    for (int o = 16; o; o >>= 1) m = fmaxf(m, __shfl_xor_sync(0xffffffffu, m, o));

    float sum = 0.f;
    for (int i = start + lane; i < end; i += 32)
        sum += __expf(lrelu(ss[csrSrc[i]] + sd) - m);
#pragma unroll
    for (int o = 16; o; o >>= 1) sum += __shfl_xor_sync(0xffffffffu, sum, o);
    float inv = 1.f / (sum + 1e-16f);

    float4 a0 = make_float4(0.f, 0.f, 0.f, 0.f);
    float4 a1 = make_float4(0.f, 0.f, 0.f, 0.f);
#pragma unroll 2
    for (int i = start; i < end; i++) {
        int s = csrSrc[i];
        float w = __expf(lrelu(ss[s] + sd) - m) * inv;
        const float4* rp = (const float4*)(Wh + (size_t)s * ld + h * hs);
        float4 u = rp[lane];
        a0.x += w * u.x; a0.y += w * u.y; a0.z += w * u.z; a0.w += w * u.w;
        if (F4 == 2) {
            float4 u2 = rp[lane + 32];
            a1.x += w * u2.x; a1.y += w * u2.y; a1.z += w * u2.z; a1.w += w * u2.w;
        }
    }

    size_t obase = (size_t)d * outld + h * ouths;
    if (mode == 1) {
        a0.x = eluf(eluf(a0.x)); a0.y = eluf(eluf(a0.y));
        a0.z = eluf(eluf(a0.z)); a0.w = eluf(eluf(a0.w));
        a1.x = eluf(eluf(a1.x)); a1.y = eluf(eluf(a1.y));
        a1.z = eluf(eluf(a1.z)); a1.w = eluf(eluf(a1.w));
    } else if (mode == 2) {
        const float4* xp = (const float4*)(xskip + obase);
        float4 p0 = xp[lane];
        a0.x = eluf(eluf(a0.x) + p0.x); a0.y = eluf(eluf(a0.y) + p0.y);
        a0.z = eluf(eluf(a0.z) + p0.z); a0.w = eluf(eluf(a0.w) + p0.w);
        if (F4 == 2) {
            float4 p1 = xp[lane + 32];
            a1.x = eluf(eluf(a1.x) + p1.x); a1.y = eluf(eluf(a1.y) + p1.y);
            a1.z = eluf(eluf(a1.z) + p1.z); a1.w = eluf(eluf(a1.w) + p1.w);
        }
    }
    float4* op = (float4*)(out + obase);
    op[lane] = a0;
    if (F4 == 2) op[lane + 32] = a1;
}

// ---------------- final: mean over 6 heads + sigmoid --------------------------
__global__ void final_k(const float* __restrict__ h3, float* __restrict__ out, int N) {
    int i = blockIdx.x * blockDim.x + threadIdx.x;
    if (i >= N * 121) return;
    int n = i / 121, f = i - n * 121;
    const float* base = h3 + (size_t)n * 768 + f;
    float v = 0.f;
#pragma unroll
    for (int h = 0; h < 6; h++) v += base[h * 128];
    v *= (1.f / 6.f);
    out[i] = 1.f / (1.f + __expf(-v));
}

// ---------------- driver ------------------------------------------------------
extern "C" void kernel_launch(void* const* d_in, const int* in_sizes, int n_in,
                              void* d_out, int out_size) {
    const float* x = (const float*)d_in[0];
    const void* ei = d_in[1];
    const float* W1 = (const float*)d_in[2];
    const float* a1 = (const float*)d_in[3];
    const float* W2 = (const float*)d_in[4];
    const float* a2 = (const float*)d_in[5];
    const float* W3 = (const float*)d_in[6];
    const float* a3 = (const float*)d_in[7];
    float* out = (float*)d_out;

    float *B, *Wh, *x1, *x2, *hb, *xp, *ssrc, *sdst;
    int *srcI, *dstI, *cnt, *rowptr, *cursor, *csrSrc;
    cudaGetSymbolAddress((void**)&B, g_B);
    cudaGetSymbolAddress((void**)&Wh, g_Wh);
    cudaGetSymbolAddress((void**)&x1, g_x1);
    cudaGetSymbolAddress((void**)&x2, g_x2);
    cudaGetSymbolAddress((void**)&hb, g_h);
    cudaGetSymbolAddress((void**)&xp, g_xp);
    cudaGetSymbolAddress((void**)&ssrc, g_ssrc);
    cudaGetSymbolAddress((void**)&sdst, g_sdst);
    cudaGetSymbolAddress((void**)&srcI, g_srcI);
    cudaGetSymbolAddress((void**)&dstI, g_dstI);
    cudaGetSymbolAddress((void**)&cnt, g_cnt);
    cudaGetSymbolAddress((void**)&rowptr, g_rowptr);
    cudaGetSymbolAddress((void**)&cursor, g_cursor);
    cudaGetSymbolAddress((void**)&csrSrc, g_csrSrc);

    static int smem_set = 0;
    if (!smem_set) {
        cudaFuncSetAttribute(gemm_tf32, cudaFuncAttributeMaxDynamicSharedMemorySize,
                             GEMM_SMEM);
        smem_set = 1;
    }

    const int N = NN, E = NE;
    const int TB = 256;

    zero_i<<<(N + TB - 1) / TB, TB>>>(cnt, N);
    detect_k<<<1, 1>>>(ei, N);
    convhist_k<<<(E + TB - 1) / TB, TB>>>(ei, srcI, dstI, cnt, E);
    scan_k<<<1, 1024>>>(cnt, rowptr, cursor, N);
    fill_k<<<(E + TB - 1) / TB, TB>>>(srcI, dstI, cursor, csrSrc, E);
    pad_x<<<(N * 64 + TB - 1) / TB, TB>>>(x, xp, N);

    // ============ Layer 1: K=50->64, H=4, F=256 ============
    {
        int K = 50, Kp = 64, H = 4, F = 256, Ntot = 1024;
        repack_w<<<(Kp * H * F + TB - 1) / TB, TB>>>(W1, B, K, Kp, H, F, F);
        zero2_k<<<(H * N + TB - 1) / TB, TB>>>(ssrc, sdst, H * N);
        dim3 g(Ntot / GBN, (N + GBM - 1) / GBM);
        gemm_tf32<<<g, 256, GEMM_SMEM>>>(N, Ntot, Kp, xp, B, Wh,
                                         a1, F, F, 2 * F, ssrc, sdst);
        agg_k<<<((size_t)N * H * 32 + TB - 1) / TB, TB>>>(N, H, 2, Ntot, F, Ntot, F, 1,
                                                          rowptr, csrSrc, ssrc, sdst, Wh,
                                                          nullptr, x1);
    }

    // ============ Layer 2: K=1024, H=4, F=256, skip ============
    {
        int K = 1024, H = 4, F = 256, Ntot = 1024;
        repack_w<<<(K * H * F + TB - 1) / TB, TB>>>(W2, B, K, K, H, F, F);
        zero2_k<<<(H * N + TB - 1) / TB, TB>>>(ssrc, sdst, H * N);
        dim3 g(Ntot / GBN, (N + GBM - 1) / GBM);
        gemm_tf32<<<g, 256, GEMM_SMEM>>>(N, Ntot, K, x1, B, Wh,
                                         a2, F, F, 2 * F, ssrc, sdst);
        agg_k<<<((size_t)N * H * 32 + TB - 1) / TB, TB>>>(N, H, 2, Ntot, F, Ntot, F, 2,
                                                          rowptr, csrSrc, ssrc, sdst, Wh,
                                                          x1, x2);
    }

    // ============ Layer 3: K=1024, H=6, F=121 (pad 128), mean heads ============
    {
        int K = 1024, H = 6, F = 121, FP = 128, Ntot = 768;
        repack_w<<<(K * H * FP + TB - 1) / TB, TB>>>(W3, B, K, K, H, F, FP);
        zero2_k<<<(H * N + TB - 1) / TB, TB>>>(ssrc, sdst, H * N);
        dim3 g(Ntot / GBN, (N + GBM - 1) / GBM);
        gemm_tf32<<<g, 256, GEMM_SMEM>>>(N, Ntot, K, x2, B, Wh,
                                         a3, F, FP, 2 * F, ssrc, sdst);
        agg_k<<<((size_t)N * H * 32 + TB - 1) / TB, TB>>>(N, H, 1, Ntot, FP, Ntot, FP, 0,
                                                          rowptr, csrSrc, ssrc, sdst, Wh,
                                                          nullptr, hb);
        final_k<<<(N * 121 + TB - 1) / TB, TB>>>(hb, out, N);
    }
}

// round 10
// speedup vs baseline: 5.4386x; 1.0203x over previous
#include <cuda_runtime.h>
#include <cstdint>
#include <cstddef>

#define NN 20000
#define NE 320000
#define ALPHA 0.2f

// ---------------- scratch (device globals; no allocation allowed) ------------
__device__ __align__(16) float g_B[1024 * 1024];
__device__ __align__(16) float g_Wh[(size_t)NN * 1024];
__device__ __align__(16) float g_x1[(size_t)NN * 1024];
__device__ __align__(16) float g_x2[(size_t)NN * 1024];
__device__ __align__(16) float g_h[(size_t)NN * 1024];
__device__ __align__(16) float g_xp[(size_t)NN * 64];
__device__ __align__(16) float g_ssrc[3 * 6 * NN];   // per-layer slices
__device__ __align__(16) float g_sdst[3 * 6 * NN];
__device__ __align__(16) int g_srcI[NE];
__device__ __align__(16) int g_dstI[NE];
__device__ __align__(16) int g_cnt[NN];
__device__ __align__(16) int g_rowptr[NN + 4];
__device__ __align__(16) int g_cursor[NN];
__device__ __align__(16) int g_csrSrc[NE];
__device__ int g_is64;

// ---------------- helpers ----------------------------------------------------
__device__ __forceinline__ float eluf(float z) { return z > 0.f ? z : expm1f(z); }
__device__ __forceinline__ float lrelu(float v) { return v > 0.f ? v : ALPHA * v; }
__device__ __forceinline__ unsigned smem_u32(const void* p) {
    return (unsigned)__cvta_generic_to_shared(p);
}
__device__ __forceinline__ void cp16(unsigned dst, const void* src, int szbytes) {
    asm volatile("cp.async.cg.shared.global [%0], [%1], 16, %2;"
                 :: "r"(dst), "l"(src), "r"(szbytes));
}
__device__ __forceinline__ void cp_commit() { asm volatile("cp.async.commit_group;"); }
template <int NWAIT>
__device__ __forceinline__ void cp_wait() {
    asm volatile("cp.async.wait_group %0;" :: "n"(NWAIT));
}

// ---------------- setup kernels -----------------------------------------------
// parallel dtype probe: int64 edge buffer has every word in [0, N)
__global__ void detect_k(const void* __restrict__ ei, int N) {
    __shared__ int bad;
    if (threadIdx.x == 0) bad = 0;
    __syncthreads();
    long long v = ((const long long*)ei)[threadIdx.x];
    if (v < 0 || v >= N) bad = 1;
    __syncthreads();
    if (threadIdx.x == 0) g_is64 = !bad;
}
// zero cnt + all 3 layers' score buffers in one pass
__global__ void zeroall_k(int* __restrict__ cnt, float* __restrict__ ssrc,
                          float* __restrict__ sdst) {
    int i = blockIdx.x * blockDim.x + threadIdx.x;
    if (i < NN) cnt[i] = 0;
    if (i < 3 * 6 * NN) { ssrc[i] = 0.f; sdst[i] = 0.f; }
}
__global__ void convhist_k(const void* __restrict__ ei, int* __restrict__ s,
                           int* __restrict__ d, int* __restrict__ cnt, int E) {
    int i = blockIdx.x * blockDim.x + threadIdx.x;
    if (i >= E) return;
    int sv, dv;
    if (g_is64) {
        const long long* p = (const long long*)ei;
        sv = (int)p[i]; dv = (int)p[E + i];
    } else {
        const int* p = (const int*)ei;
        sv = p[i]; dv = p[E + i];
    }
    s[i] = sv; d[i] = dv;
    atomicAdd(&cnt[dv], 1);
}
// single-block warp-shfl scan; seeds cursor with exclusive prefix
__global__ void scan_k(const int* __restrict__ cnt, int* __restrict__ rowptr,
                       int* __restrict__ cursor, int n) {
    __shared__ int sums[32];
    __shared__ int carry;
    const int t = threadIdx.x;
    const int lane = t & 31, wid = t >> 5;
    if (t == 0) { carry = 0; rowptr[0] = 0; }
    __syncthreads();
    for (int base = 0; base < n; base += 1024) {
        int i = base + t;
        int v = (i < n) ? cnt[i] : 0;
        int x = v;
#pragma unroll
        for (int o = 1; o < 32; o <<= 1) {
            int y = __shfl_up_sync(0xffffffffu, x, o);
            if (lane >= o) x += y;
        }
        if (lane == 31) sums[wid] = x;
        __syncthreads();
        if (wid == 0) {
            int s = sums[lane];
#pragma unroll
            for (int o = 1; o < 32; o <<= 1) {
                int y = __shfl_up_sync(0xffffffffu, s, o);
                if (lane >= o) s += y;
            }
            sums[lane] = s;
        }
        __syncthreads();
        int incl = x + (wid ? sums[wid - 1] : 0) + carry;
        if (i < n) {
            rowptr[i + 1] = incl;
            cursor[i] = incl - v;
        }
        __syncthreads();
        if (t == 0) carry += sums[31];
        __syncthreads();
    }
}
__global__ void fill_k(const int* __restrict__ src, const int* __restrict__ dst,
                       int* __restrict__ cursor, int* __restrict__ csrSrc, int E) {
    int i = blockIdx.x * blockDim.x + threadIdx.x;
    if (i >= E) return;
    int pos = atomicAdd(&cursor[dst[i]], 1);
    csrSrc[pos] = src[i];
}
__global__ void pad_x(const float* __restrict__ x, float* __restrict__ xp, int N) {
    int i = blockIdx.x * blockDim.x + threadIdx.x;
    if (i >= N * 64) return;
    int n = i >> 6, c = i & 63;
    xp[i] = (c < 50) ? x[n * 50 + c] : 0.f;
}
__global__ void repack_w(const float* __restrict__ W, float* __restrict__ B,
                         int K, int Kp, int H, int F, int FP) {
    int total = Kp * H * FP;
    int idx = blockIdx.x * blockDim.x + threadIdx.x;
    if (idx >= total) return;
    int hf = H * FP;
    int k = idx / hf;
    int rem = idx - k * hf;
    int h = rem / FP;
    int f = rem - h * FP;
    B[idx] = (k < K && f < F) ? W[((size_t)h * K + k) * F + f] : 0.f;
}

// ---------------- TF32 GEMM, 3-stage cp.async, fused attention scores ---------
#define GBM 128
#define GBN 128
#define GBK 16
#define APAD 20
#define BPAD 136
#define AS_WORDS (GBM * APAD)
#define BS_WORDS (GBK * BPAD)
#define STAGE_WORDS (AS_WORDS + BS_WORDS)
#define GEMM_SMEM (3 * STAGE_WORDS * 4)

__global__ __launch_bounds__(256) void gemm_tf32(int M, int N, int K,
                                                 const float* __restrict__ A,
                                                 const float* __restrict__ B,
                                                 float* __restrict__ C,
                                                 const float* __restrict__ aVec,
                                                 int F, int hs, int astride,
                                                 float* __restrict__ ssrc,
                                                 float* __restrict__ sdst) {
    extern __shared__ float sm[];

    const int tid = threadIdx.x;
    const int warp = tid >> 5;
    const int lane = tid & 31;
    const int g = lane >> 2;
    const int tig = lane & 3;
    const int wm = warp & 1;
    const int wn = warp >> 1;
    const int bm = blockIdx.y * GBM;
    const int bn = blockIdx.x * GBN;

    const int ar0 = tid >> 2, ac0 = (tid & 3) * 4;
    const int ar1 = (tid + 256) >> 2;
    const int bk0 = tid >> 5, bc0 = (tid & 31) * 4;
    const int bk1 = (tid + 256) >> 5;

    float acc[4][4][4];
#pragma unroll
    for (int mf = 0; mf < 4; mf++)
#pragma unroll
        for (int nf = 0; nf < 4; nf++)
#pragma unroll
            for (int r = 0; r < 4; r++) acc[mf][nf][r] = 0.f;

    const int KT = K / GBK;

    auto issue = [&](int kt, int stg) {
        float* As = sm + stg * STAGE_WORDS;
        float* Bs = As + AS_WORDS;
        const int k0 = kt * GBK;
        cp16(smem_u32(As + ar0 * APAD + ac0), A + (size_t)(bm + ar0) * K + k0 + ac0,
             (bm + ar0 < M) ? 16 : 0);
        cp16(smem_u32(As + ar1 * APAD + ac0), A + (size_t)(bm + ar1) * K + k0 + ac0,
             (bm + ar1 < M) ? 16 : 0);
        cp16(smem_u32(Bs + bk0 * BPAD + bc0), B + (size_t)(k0 + bk0) * N + bn + bc0, 16);
        cp16(smem_u32(Bs + bk1 * BPAD + bc0), B + (size_t)(k0 + bk1) * N + bn + bc0, 16);
    };

    issue(0, 0); cp_commit();
    if (KT > 1) issue(1, 1);
    cp_commit();

    int stg = 0, stg2 = (KT > 2) ? 2 : (KT == 2 ? 0 : 1);
    for (int kt = 0; kt < KT; kt++) {
        cp_wait<1>();
        __syncthreads();
        if (kt + 2 < KT) issue(kt + 2, stg2);
        cp_commit();

        const float* As = sm + stg * STAGE_WORDS;
        const float* Bs = As + AS_WORDS;
#pragma unroll
        for (int ks = 0; ks < 2; ks++) {
            const int kc = ks * 8;
            unsigned af[4][4], bf[4][2];
#pragma unroll
            for (int mf = 0; mf < 4; mf++) {
                int r = wm * 64 + mf * 16;
                af[mf][0] = __float_as_uint(As[(r + g) * APAD + kc + tig]);
                af[mf][1] = __float_as_uint(As[(r + g + 8) * APAD + kc + tig]);
                af[mf][2] = __float_as_uint(As[(r + g) * APAD + kc + tig + 4]);
                af[mf][3] = __float_as_uint(As[(r + g + 8) * APAD + kc + tig + 4]);
            }
#pragma unroll
            for (int nf = 0; nf < 4; nf++) {
                int c = wn * 32 + nf * 8 + g;
                bf[nf][0] = __float_as_uint(Bs[(kc + tig) * BPAD + c]);
                bf[nf][1] = __float_as_uint(Bs[(kc + tig + 4) * BPAD + c]);
            }
#pragma unroll
            for (int mf = 0; mf < 4; mf++)
#pragma unroll
                for (int nf = 0; nf < 4; nf++) {
                    asm volatile(
                        "mma.sync.aligned.m16n8k8.row.col.f32.tf32.tf32.f32 "
                        "{%0,%1,%2,%3}, {%4,%5,%6,%7}, {%8,%9}, {%0,%1,%2,%3};"
                        : "+f"(acc[mf][nf][0]), "+f"(acc[mf][nf][1]),
                          "+f"(acc[mf][nf][2]), "+f"(acc[mf][nf][3])
                        : "r"(af[mf][0]), "r"(af[mf][1]), "r"(af[mf][2]), "r"(af[mf][3]),
                          "r"(bf[nf][0]), "r"(bf[nf][1]));
                }
        }
        stg = (stg + 1 == 3) ? 0 : stg + 1;
        stg2 = (stg2 + 1 == 3) ? 0 : stg2 + 1;
    }

    // ---- store C ----
#pragma unroll
    for (int mf = 0; mf < 4; mf++) {
        int r0 = bm + wm * 64 + mf * 16 + g;
#pragma unroll
        for (int nf = 0; nf < 4; nf++) {
            int c0 = bn + wn * 32 + nf * 8 + tig * 2;
            if (r0 < M) {
                float2 v = make_float2(acc[mf][nf][0], acc[mf][nf][1]);
                *(float2*)(C + (size_t)r0 * N + c0) = v;
            }
            if (r0 + 8 < M) {
                float2 v = make_float2(acc[mf][nf][2], acc[mf][nf][3]);
                *(float2*)(C + (size_t)(r0 + 8) * N + c0) = v;
            }
        }
    }

    // ---- fused attention-score partial dot ----
    {
        const int h0 = bn / hs;
        const int cbase = bn % hs;
        const float* av = aVec + (size_t)h0 * astride;
        float as_[8], ad_[8];
#pragma unroll
        for (int nf = 0; nf < 4; nf++)
#pragma unroll
            for (int e = 0; e < 2; e++) {
                int cf = cbase + wn * 32 + nf * 8 + tig * 2 + e;
                bool ok = cf < F;
                as_[nf * 2 + e] = ok ? av[cf] : 0.f;
                ad_[nf * 2 + e] = ok ? av[F + cf] : 0.f;
            }
#pragma unroll
        for (int mf = 0; mf < 4; mf++) {
            float s0 = 0.f, d0 = 0.f, s1 = 0.f, d1 = 0.f;
#pragma unroll
            for (int nf = 0; nf < 4; nf++)
#pragma unroll
                for (int e = 0; e < 2; e++) {
                    int idx = nf * 2 + e;
                    s0 += acc[mf][nf][e] * as_[idx];
                    d0 += acc[mf][nf][e] * ad_[idx];
                    s1 += acc[mf][nf][2 + e] * as_[idx];
                    d1 += acc[mf][nf][2 + e] * ad_[idx];
                }
#pragma unroll
            for (int o = 1; o <= 2; o <<= 1) {
                s0 += __shfl_xor_sync(0xffffffffu, s0, o);
                d0 += __shfl_xor_sync(0xffffffffu, d0, o);
                s1 += __shfl_xor_sync(0xffffffffu, s1, o);
                d1 += __shfl_xor_sync(0xffffffffu, d1, o);
            }
            if (tig == 0) {
                int r0 = bm + wm * 64 + mf * 16 + g;
                if (r0 < M) {
                    atomicAdd(&ssrc[h0 * NN + r0], s0);
                    atomicAdd(&sdst[h0 * NN + r0], d0);
                }
                if (r0 + 8 < M) {
                    atomicAdd(&ssrc[h0 * NN + r0 + 8], s1);
                    atomicAdd(&sdst[h0 * NN + r0 + 8], d1);
                }
            }
        }
    }
}

// ---------------- fused online-softmax + gather aggregation + epilogue --------
__global__ void agg_k(int N, int H, int F4, int ld, int hs, int outld, int ouths,
                      int mode,
                      const int* __restrict__ rowptr, const int* __restrict__ csrSrc,
                      const float* __restrict__ ssrc, const float* __restrict__ sdst,
                      const float* __restrict__ Wh, const float* __restrict__ xskip,
                      float* __restrict__ out) {
    int gw = (blockIdx.x * blockDim.x + threadIdx.x) >> 5;
    if (gw >= N * H) return;
    int lane = threadIdx.x & 31;
    int d = gw / H, h = gw - d * H;
    int start = rowptr[d], end = rowptr[d + 1];
    float sd = sdst[h * N + d];
    const float* ss = ssrc + (size_t)h * N;

    // single-pass online softmax (per-lane running max/sum, then warp merge)
    float m = -1e30f, s = 0.f;
    for (int i = start + lane; i < end; i += 32) {
        float v = lrelu(ss[csrSrc[i]] + sd);
        if (v > m) { s = s * __expf(m - v) + 1.f; m = v; }
        else s += __expf(v - m);
    }
#pragma unroll
    for (int o = 16; o; o >>= 1) {
        float mo = __shfl_xor_sync(0xffffffffu, m, o);
        float so = __shfl_xor_sync(0xffffffffu, s, o);
        float M = fmaxf(m, mo);
        s = s * __expf(m - M) + so * __expf(mo - M);
        m = M;
    }
    float inv = 1.f / (s + 1e-16f);

    float4 a0 = make_float4(0.f, 0.f, 0.f, 0.f);
    float4 a1 = make_float4(0.f, 0.f, 0.f, 0.f);
#pragma unroll 2
    for (int i = start; i < end; i++) {
        int sidx = csrSrc[i];
        float w = __expf(lrelu(ss[sidx] + sd) - m) * inv;
        const float4* rp = (const float4*)(Wh + (size_t)sidx * ld + h * hs);
        float4 u = rp[lane];
        a0.x += w * u.x; a0.y += w * u.y; a0.z += w * u.z; a0.w += w * u.w;
        if (F4 == 2) {
            float4 u2 = rp[lane + 32];
            a1.x += w * u2.x; a1.y += w * u2.y; a1.z += w * u2.z; a1.w += w * u2.w;
        }
    }

    size_t obase = (size_t)d * outld + h * ouths;
    if (mode == 1) {
        a0.x = eluf(eluf(a0.x)); a0.y = eluf(eluf(a0.y));
        a0.z = eluf(eluf(a0.z)); a0.w = eluf(eluf(a0.w));
        a1.x = eluf(eluf(a1.x)); a1.y = eluf(eluf(a1.y));
        a1.z = eluf(eluf(a1.z)); a1.w = eluf(eluf(a1.w));
    } else if (mode == 2) {
        const float4* xp = (const float4*)(xskip + obase);
        float4 p0 = xp[lane];
        a0.x = eluf(eluf(a0.x) + p0.x); a0.y = eluf(eluf(a0.y) + p0.y);
        a0.z = eluf(eluf(a0.z) + p0.z); a0.w = eluf(eluf(a0.w) + p0.w);
        if (F4 == 2) {
            float4 p1 = xp[lane + 32];
            a1.x = eluf(eluf(a1.x) + p1.x); a1.y = eluf(eluf(a1.y) + p1.y);
            a1.z = eluf(eluf(a1.z) + p1.z); a1.w = eluf(eluf(a1.w) + p1.w);
        }
    }
    float4* op = (float4*)(out + obase);
    op[lane] = a0;
    if (F4 == 2) op[lane + 32] = a1;
}

// ---------------- final: mean over 6 heads + sigmoid --------------------------
__global__ void final_k(const float* __restrict__ h3, float* __restrict__ out, int N) {
    int i = blockIdx.x * blockDim.x + threadIdx.x;
    if (i >= N * 121) return;
    int n = i / 121, f = i - n * 121;
    const float* base = h3 + (size_t)n * 768 + f;
    float v = 0.f;
#pragma unroll
    for (int h = 0; h < 6; h++) v += base[h * 128];
    v *= (1.f / 6.f);
    out[i] = 1.f / (1.f + __expf(-v));
}

// ---------------- driver ------------------------------------------------------
extern "C" void kernel_launch(void* const* d_in, const int* in_sizes, int n_in,
                              void* d_out, int out_size) {
    const float* x = (const float*)d_in[0];
    const void* ei = d_in[1];
    const float* W1 = (const float*)d_in[2];
    const float* a1 = (const float*)d_in[3];
    const float* W2 = (const float*)d_in[4];
    const float* a2 = (const float*)d_in[5];
    const float* W3 = (const float*)d_in[6];
    const float* a3 = (const float*)d_in[7];
    float* out = (float*)d_out;

    float *B, *Wh, *x1, *x2, *hb, *xp, *ssrc, *sdst;
    int *srcI, *dstI, *cnt, *rowptr, *cursor, *csrSrc;
    cudaGetSymbolAddress((void**)&B, g_B);
    cudaGetSymbolAddress((void**)&Wh, g_Wh);
    cudaGetSymbolAddress((void**)&x1, g_x1);
    cudaGetSymbolAddress((void**)&x2, g_x2);
    cudaGetSymbolAddress((void**)&hb, g_h);
    cudaGetSymbolAddress((void**)&xp, g_xp);
    cudaGetSymbolAddress((void**)&ssrc, g_ssrc);
    cudaGetSymbolAddress((void**)&sdst, g_sdst);
    cudaGetSymbolAddress((void**)&srcI, g_srcI);
    cudaGetSymbolAddress((void**)&dstI, g_dstI);
    cudaGetSymbolAddress((void**)&cnt, g_cnt);
    cudaGetSymbolAddress((void**)&rowptr, g_rowptr);
    cudaGetSymbolAddress((void**)&cursor, g_cursor);
    cudaGetSymbolAddress((void**)&csrSrc, g_csrSrc);

    static int smem_set = 0;
    if (!smem_set) {
        cudaFuncSetAttribute(gemm_tf32, cudaFuncAttributeMaxDynamicSharedMemorySize,
                             GEMM_SMEM);
        smem_set = 1;
    }

    const int N = NN, E = NE;
    const int TB = 256;
    float* ss0 = ssrc;              float* sd0 = sdst;
    float* ss1 = ssrc + 6 * NN;     float* sd1 = sdst + 6 * NN;
    float* ss2 = ssrc + 12 * NN;    float* sd2 = sdst + 12 * NN;

    zeroall_k<<<(3 * 6 * N + TB - 1) / TB, TB>>>(cnt, ssrc, sdst);
    detect_k<<<1, 1024>>>(ei, N);
    convhist_k<<<(E + TB - 1) / TB, TB>>>(ei, srcI, dstI, cnt, E);
    scan_k<<<1, 1024>>>(cnt, rowptr, cursor, N);
    fill_k<<<(E + TB - 1) / TB, TB>>>(srcI, dstI, cursor, csrSrc, E);
    pad_x<<<(N * 64 + TB - 1) / TB, TB>>>(x, xp, N);

    // ============ Layer 1: K=50->64, H=4, F=256 ============
    {
        int K = 50, Kp = 64, H = 4, F = 256, Ntot = 1024;
        repack_w<<<(Kp * H * F + TB - 1) / TB, TB>>>(W1, B, K, Kp, H, F, F);
        dim3 g(Ntot / GBN, (N + GBM - 1) / GBM);
        gemm_tf32<<<g, 256, GEMM_SMEM>>>(N, Ntot, Kp, xp, B, Wh,
                                         a1, F, F, 2 * F, ss0, sd0);
        agg_k<<<((size_t)N * H * 32 + TB - 1) / TB, TB>>>(N, H, 2, Ntot, F, Ntot, F, 1,
                                                          rowptr, csrSrc, ss0, sd0, Wh,
                                                          nullptr, x1);
    }

    // ============ Layer 2: K=1024, H=4, F=256, skip ============
    {
        int K = 1024, H = 4, F = 256, Ntot = 1024;
        repack_w<<<(K * H * F + TB - 1) / TB, TB>>>(W2, B, K, K, H, F, F);
        dim3 g(Ntot / GBN, (N + GBM - 1) / GBM);
        gemm_tf32<<<g, 256, GEMM_SMEM>>>(N, Ntot, K, x1, B, Wh,
                                         a2, F, F, 2 * F, ss1, sd1);
        agg_k<<<((size_t)N * H * 32 + TB - 1) / TB, TB>>>(N, H, 2, Ntot, F, Ntot, F, 2,
                                                          rowptr, csrSrc, ss1, sd1, Wh,
                                                          x1, x2);
    }

    // ============ Layer 3: K=1024, H=6, F=121 (pad 128), mean heads ============
    {
        int K = 1024, H = 6, F = 121, FP = 128, Ntot = 768;
        repack_w<<<(K * H * FP + TB - 1) / TB, TB>>>(W3, B, K, K, H, F, FP);
        dim3 g(Ntot / GBN, (N + GBM - 1) / GBM);
        gemm_tf32<<<g, 256, GEMM_SMEM>>>(N, Ntot, K, x2, B, Wh,
                                         a3, F, FP, 2 * F, ss2, sd2);
        agg_k<<<((size_t)N * H * 32 + TB - 1) / TB, TB>>>(N, H, 1, Ntot, FP, Ntot, FP, 0,
                                                          rowptr, csrSrc, ss2, sd2, Wh,
                                                          nullptr, hb);
        final_k<<<(N * 121 + TB - 1) / TB, TB>>>(hb, out, N);
    }
}